// round 9
// baseline (speedup 1.0000x reference)
#include <cuda_runtime.h>
#include <cuda_bf16.h>
#include <cstdint>

// ---------------------------------------------------------------------------
// Transformer-XL masked MHA. S=1024, P=1024, J=2048, B=2, E=1024, H=16, I=64.
// All GEMMs + flash attention on mma.sync m16n8k16 bf16 (3-term split).
// GEMM core = Round-6 schedule. Flash = cp.async software-pipelined K/V loads.
// ---------------------------------------------------------------------------

constexpr int S_   = 1024;
constexpr int P_   = 1024;
constexpr int B_   = 2;
constexpr int E_   = 1024;
constexpr int H_   = 16;
constexpr int I_   = 64;
constexpr int J_   = 2048;
constexpr int HI_  = 1024;
constexpr float SCALE_ = 0.125f;
constexpr float EPS_   = 1e-5f;

// ------------------------- scratch (device globals) ------------------------
__device__ __nv_bfloat16 g_Khi [(size_t)B_*H_*J_*I_];  // [bh][j][i]
__device__ __nv_bfloat16 g_Klo [(size_t)B_*H_*J_*I_];
__device__ __nv_bfloat16 g_Vthi[(size_t)B_*H_*I_*J_];  // [bh][i][j] (transposed)
__device__ __nv_bfloat16 g_Vtlo[(size_t)B_*H_*I_*J_];
__device__ __nv_bfloat16 g_quhi[(size_t)B_*H_*S_*I_];  // [bh][s][i]
__device__ __nv_bfloat16 g_qulo[(size_t)B_*H_*S_*I_];
__device__ float g_qv  [(size_t)B_*H_*S_*I_];
__device__ float g_pos [(size_t)H_*J_*I_];
__device__ __nv_bfloat16 g_PD [(size_t)B_*H_*S_*J_];   // pre-shifted [bh][s][j]
__device__ float g_ctx [(size_t)S_*B_*HI_];
__device__ float g_proj[(size_t)S_*B_*E_];

// ------------------------------ helpers ------------------------------------
__device__ __forceinline__ void split1(float x, __nv_bfloat16& h, __nv_bfloat16& l) {
    h = __float2bfloat16(x);
    l = __float2bfloat16(x - __bfloat162float(h));
}
__device__ __forceinline__ void split2(float x, float y,
                                       uint32_t& hi, uint32_t& lo) {
    __nv_bfloat162 h = __floats2bfloat162_rn(x, y);
    __nv_bfloat162 l = __floats2bfloat162_rn(x - __bfloat162float(h.x),
                                             y - __bfloat162float(h.y));
    hi = *(const uint32_t*)&h;
    lo = *(const uint32_t*)&l;
}
__device__ __forceinline__ void mma_bf16(float* d, const uint32_t* a,
                                         const uint32_t* b) {
    asm volatile(
        "mma.sync.aligned.m16n8k16.row.col.f32.bf16.bf16.f32 "
        "{%0,%1,%2,%3}, {%4,%5,%6,%7}, {%8,%9}, {%0,%1,%2,%3};"
        : "+f"(d[0]), "+f"(d[1]), "+f"(d[2]), "+f"(d[3])
        : "r"(a[0]), "r"(a[1]), "r"(a[2]), "r"(a[3]), "r"(b[0]), "r"(b[1]));
}

#define CP_ASYNC16(dst_u32, src_ptr) \
    asm volatile("cp.async.cg.shared.global [%0], [%1], 16;" \
                 :: "r"(dst_u32), "l"(src_ptr) : "memory")
#define CP_COMMIT() asm volatile("cp.async.commit_group;" ::: "memory")
#define CP_WAIT1()  asm volatile("cp.async.wait_group 1;" ::: "memory")
#define CP_WAIT0()  asm volatile("cp.async.wait_group 0;" ::: "memory")

// ------------------------------- functors ----------------------------------
struct ALoadKV {
    const float* mem; const float* x;
    __device__ __forceinline__ float4 operator()(int, int m, int k) const {
        const float* p = (m < P_*B_) ? (mem + (size_t)m*E_ + k)
                                     : (x + (size_t)(m - P_*B_)*E_ + k);
        return *(const float4*)p;
    }
};
struct ALoadPlain {
    const float* a; int K;
    __device__ __forceinline__ float4 operator()(int, int m, int k) const {
        return *(const float4*)(a + (size_t)m*K + k);
    }
};
struct ALoadQV {
    __device__ __forceinline__ float4 operator()(int bz, int m, int k) const {
        return *(const float4*)&g_qv[((size_t)bz*S_ + m)*I_ + k];
    }
};
struct ALoadCtx {
    __device__ __forceinline__ float4 operator()(int, int m, int k) const {
        return *(const float4*)&g_ctx[(size_t)m*HI_ + k];
    }
};
struct BLoadW {
    const float* w; int K;
    __device__ __forceinline__ float4 operator()(int, int n, int k) const {
        return *(const float4*)(w + (size_t)n*K + k);
    }
};
struct BLoadPos {
    __device__ __forceinline__ float4 operator()(int bz, int n, int k) const {
        return *(const float4*)&g_pos[((size_t)(bz % H_)*J_ + n)*I_ + k];
    }
};

struct CStoreKV {
    static constexpr bool kSkipPD = false;
    __device__ __forceinline__ void operator()(int, int m, int n, float c) const {
        int j = m / B_, b = m % B_;
        __nv_bfloat16 h, l;
        split1(c, h, l);
        if (n < HI_) {
            int hh = n >> 6, i = n & 63;
            size_t o = (((size_t)(b*H_ + hh))*J_ + j)*I_ + i;
            g_Khi[o] = h; g_Klo[o] = l;
        } else {
            int n2 = n - HI_; int hh = n2 >> 6, i = n2 & 63;
            size_t o = (((size_t)(b*H_ + hh))*I_ + i)*J_ + j;  // transposed
            g_Vthi[o] = h; g_Vtlo[o] = l;
        }
    }
};
struct CStoreQ {
    static constexpr bool kSkipPD = false;
    const float* u; const float* v;
    __device__ __forceinline__ void operator()(int, int m, int n, float c) const {
        int s = m / B_, b = m % B_;
        int hh = n >> 6, i = n & 63;
        size_t o = (((size_t)(b*H_ + hh))*S_ + s)*I_ + i;
        float qu = c + u[n];
        __nv_bfloat16 h, l;
        split1(qu, h, l);
        g_quhi[o] = h; g_qulo[o] = l;
        g_qv[o] = c + v[n];
    }
};
struct CStorePos {
    static constexpr bool kSkipPD = false;
    __device__ __forceinline__ void operator()(int, int m, int n, float c) const {
        int hh = n >> 6, i = n & 63;
        g_pos[((size_t)hh*J_ + m)*I_ + i] = c;
    }
};
struct CStorePD {
    static constexpr bool kSkipPD = true;   // tiles with m0+n0<=768 fully dropped
    __device__ __forceinline__ void operator()(int bz, int m, int n, float c) const {
        int j = n + m - 1023;
        if (j >= 0) g_PD[((size_t)bz*S_ + m)*J_ + j] = __float2bfloat16(c);
    }
};
struct CStoreProj {
    static constexpr bool kSkipPD = false;
    const float* x;
    __device__ __forceinline__ void operator()(int, int m, int n, float c) const {
        g_proj[(size_t)m*E_ + n] = c + x[(size_t)m*E_ + n];
    }
};

// ------------------------- mma.sync GEMM (split-bf16) ----------------------
// Round-6 schedule: store chunk -> sync -> prefetch next -> compute -> sync.
constexpr int SROW = 40;   // bf16 elements per smem row (32 data + 8 pad)

template<class AL, class BL, class CS>
__global__ void __launch_bounds__(256)
gemm_mma(AL aload, BL bload, CS cstore, int K) {
    __shared__ __nv_bfloat16 sA[2][128 * SROW];
    __shared__ __nv_bfloat16 sB[2][128 * SROW];

    const int tid  = threadIdx.x;
    const int wid  = tid >> 5;
    const int lane = tid & 31;
    const int gid  = lane >> 2;
    const int tig  = lane & 3;
    const int wm   = wid >> 2;
    const int wn   = wid & 3;
    const int m0   = blockIdx.y * 128;
    const int n0   = blockIdx.x * 128;
    const int bz   = blockIdx.z;

    if constexpr (CS::kSkipPD) {
        if (m0 + n0 <= 768) return;   // all j = n+m-1023 < 0 -> nothing stored
    }

    float c[4][4][4];
#pragma unroll
    for (int mt = 0; mt < 4; mt++)
#pragma unroll
        for (int nt = 0; nt < 4; nt++)
#pragma unroll
            for (int r = 0; r < 4; r++) c[mt][nt][r] = 0.f;

    float4 av[4], bv[4];
#pragma unroll
    for (int q = 0; q < 4; q++) {
        const int f = tid + q * 256, row = f >> 3, kq = (f & 7) * 4;
        av[q] = aload(bz, m0 + row, kq);
        bv[q] = bload(bz, n0 + row, kq);
    }

    for (int k0 = 0; k0 < K; k0 += 32) {
        // ---- store current chunk (split hi/lo) ----
#pragma unroll
        for (int q = 0; q < 4; q++) {
            const int f = tid + q * 256, row = f >> 3, kq = (f & 7) * 4;
            const int so = row * SROW + kq;
            uint32_t h0, l0, h1, l1;
            split2(av[q].x, av[q].y, h0, l0);
            split2(av[q].z, av[q].w, h1, l1);
            *(uint2*)&sA[0][so] = make_uint2(h0, h1);
            *(uint2*)&sA[1][so] = make_uint2(l0, l1);
            split2(bv[q].x, bv[q].y, h0, l0);
            split2(bv[q].z, bv[q].w, h1, l1);
            *(uint2*)&sB[0][so] = make_uint2(h0, h1);
            *(uint2*)&sB[1][so] = make_uint2(l0, l1);
        }
        __syncthreads();

        // ---- prefetch next chunk ----
        if (k0 + 32 < K) {
#pragma unroll
            for (int q = 0; q < 4; q++) {
                const int f = tid + q * 256, row = f >> 3, kq = (f & 7) * 4;
                av[q] = aload(bz, m0 + row, k0 + 32 + kq);
                bv[q] = bload(bz, n0 + row, k0 + 32 + kq);
            }
        }

        // ---- compute ----
#pragma unroll
        for (int ks = 0; ks < 2; ks++) {
            const int kk = ks * 16 + tig * 2;
            uint32_t ah[4][4], al[4][4];
#pragma unroll
            for (int mt = 0; mt < 4; mt++) {
                const int m = wm * 64 + mt * 16 + gid;
                ah[mt][0] = *(const uint32_t*)&sA[0][m * SROW + kk];
                ah[mt][1] = *(const uint32_t*)&sA[0][(m + 8) * SROW + kk];
                ah[mt][2] = *(const uint32_t*)&sA[0][m * SROW + kk + 8];
                ah[mt][3] = *(const uint32_t*)&sA[0][(m + 8) * SROW + kk + 8];
                al[mt][0] = *(const uint32_t*)&sA[1][m * SROW + kk];
                al[mt][1] = *(const uint32_t*)&sA[1][(m + 8) * SROW + kk];
                al[mt][2] = *(const uint32_t*)&sA[1][m * SROW + kk + 8];
                al[mt][3] = *(const uint32_t*)&sA[1][(m + 8) * SROW + kk + 8];
            }
#pragma unroll
            for (int nt = 0; nt < 4; nt++) {
                const int n = wn * 32 + nt * 8 + gid;
                uint32_t bh[2], bl[2];
                bh[0] = *(const uint32_t*)&sB[0][n * SROW + kk];
                bh[1] = *(const uint32_t*)&sB[0][n * SROW + kk + 8];
                bl[0] = *(const uint32_t*)&sB[1][n * SROW + kk];
                bl[1] = *(const uint32_t*)&sB[1][n * SROW + kk + 8];
#pragma unroll
                for (int mt = 0; mt < 4; mt++) {
                    mma_bf16(c[mt][nt], ah[mt], bh);
                    mma_bf16(c[mt][nt], ah[mt], bl);
                    mma_bf16(c[mt][nt], al[mt], bh);
                }
            }
        }
        __syncthreads();
    }

#pragma unroll
    for (int mt = 0; mt < 4; mt++) {
        const int gm = m0 + wm * 64 + mt * 16 + gid;
#pragma unroll
        for (int nt = 0; nt < 4; nt++) {
            const int gn = n0 + wn * 32 + nt * 8 + tig * 2;
            cstore(bz, gm,     gn,     c[mt][nt][0]);
            cstore(bz, gm,     gn + 1, c[mt][nt][1]);
            cstore(bz, gm + 8, gn,     c[mt][nt][2]);
            cstore(bz, gm + 8, gn + 1, c[mt][nt][3]);
        }
    }
}

// ---------------------------- flash attention (MMA) ------------------------
// grid (S/128, B*H), 256 threads = 8 warps; warp wq owns rows wq*16..+15.
// j-tiles of 64, K/V loads software-pipelined with cp.async:
//   scores_t overlap V_t load-completion; PV_t overlaps K_{t+1} load.
constexpr int FPAD = 72;   // bf16 elems per smem row (64 data + 8 pad) = 36 words
constexpr int FLASH_SMEM = (128 + 64 + 64) * FPAD * 2 * 2;  // 73728 B

__global__ void __launch_bounds__(256) flash_mma() {
    extern __shared__ __nv_bfloat16 fsm[];
    __nv_bfloat16* sQh = fsm;                    // [s][i] 128x72
    __nv_bfloat16* sQl = sQh + 128 * FPAD;
    __nv_bfloat16* sKh = sQl + 128 * FPAD;       // [j][i] 64x72
    __nv_bfloat16* sKl = sKh + 64 * FPAD;
    __nv_bfloat16* sVh = sKl + 64 * FPAD;        // [i][j] 64x72
    __nv_bfloat16* sVl = sVh + 64 * FPAD;

    const int tid  = threadIdx.x;
    const int wq   = tid >> 5;
    const int lane = tid & 31;
    const int gid  = lane >> 2;
    const int tig  = lane & 3;
    // heavy s-blocks (more j-tiles) launch first -> better tail balance
    const int s0   = (gridDim.x - 1 - blockIdx.x) * 128;
    const int bh   = blockIdx.y;

    const int s_r0 = s0 + wq * 16 + gid;
    const int s_r1 = s_r0 + 8;

    // cp.async tile-fill geometry: 64 rows, 32 words/row; 4 threads/row
    const int row4 = tid >> 2;            // 0..63
    const int qw   = (tid & 3) * 8;       // word offset 0/8/16/24 (32B = 2x16B)

    auto issueK = [&](int j0) {
        const char* srch = (const char*)((const uint32_t*)
            (g_Khi + (((size_t)bh * J_) + j0 + row4) * I_) + qw);
        const char* srcl = (const char*)((const uint32_t*)
            (g_Klo + (((size_t)bh * J_) + j0 + row4) * I_) + qw);
        uint32_t dh = (uint32_t)__cvta_generic_to_shared(
            (uint32_t*)&sKh[row4 * FPAD] + qw);
        uint32_t dl = (uint32_t)__cvta_generic_to_shared(
            (uint32_t*)&sKl[row4 * FPAD] + qw);
        CP_ASYNC16(dh,      srch);
        CP_ASYNC16(dh + 16, srch + 16);
        CP_ASYNC16(dl,      srcl);
        CP_ASYNC16(dl + 16, srcl + 16);
    };
    auto issueV = [&](int j0) {
        const char* srch = (const char*)((const uint32_t*)
            (g_Vthi + ((size_t)bh * I_ + row4) * J_ + j0) + qw);
        const char* srcl = (const char*)((const uint32_t*)
            (g_Vtlo + ((size_t)bh * I_ + row4) * J_ + j0) + qw);
        uint32_t dh = (uint32_t)__cvta_generic_to_shared(
            (uint32_t*)&sVh[row4 * FPAD] + qw);
        uint32_t dl = (uint32_t)__cvta_generic_to_shared(
            (uint32_t*)&sVl[row4 * FPAD] + qw);
        CP_ASYNC16(dh,      srch);
        CP_ASYNC16(dh + 16, srch + 16);
        CP_ASYNC16(dl,      srcl);
        CP_ASYNC16(dl + 16, srcl + 16);
    };

    // prologue: start K_0 and V_0 (groups G1, G2)
    issueK(0); CP_COMMIT();
    issueV(0); CP_COMMIT();

    // ---- load Q tile (plain loads; overlaps with in-flight K/V) ----
    {
        const int row  = tid >> 1;
        const int half = (tid & 1) * 16;                       // word offset
        const uint4* srch = (const uint4*)((const uint32_t*)
            (g_quhi + ((size_t)bh * S_ + s0 + row) * I_) + half);
        const uint4* srcl = (const uint4*)((const uint32_t*)
            (g_qulo + ((size_t)bh * S_ + s0 + row) * I_) + half);
        uint4* dsth = (uint4*)((uint32_t*)&sQh[row * FPAD] + half);
        uint4* dstl = (uint4*)((uint32_t*)&sQl[row * FPAD] + half);
#pragma unroll
        for (int q = 0; q < 4; q++) { dsth[q] = srch[q]; dstl[q] = srcl[q]; }
    }

    const __nv_bfloat16* PDb = g_PD + (size_t)bh * S_ * J_;

    float m_[2] = {-3.0e38f, -3.0e38f};
    float l_[2] = {0.f, 0.f};
    float o[8][4];
#pragma unroll
    for (int nt = 0; nt < 8; nt++)
#pragma unroll
        for (int r = 0; r < 4; r++) o[nt][r] = 0.f;

    const int ntiles = min(32, s0 / 64 + 18);
    for (int jt = 0; jt < ntiles; jt++) {
        const int j0 = jt * 64;
        const int jn = min(jt + 1, ntiles - 1) * 64;   // clamped prefetch

        // K_t complete (all groups but newest 1); V_t may still be in flight
        CP_WAIT1();
        __syncthreads();

        // ---- scores S = Q @ K^T (128x64 per block, 16x64 per warp) ----
        float sc[8][4];
#pragma unroll
        for (int nt = 0; nt < 8; nt++)
#pragma unroll
            for (int r = 0; r < 4; r++) sc[nt][r] = 0.f;

        const uint32_t* qh32 = (const uint32_t*)sQh;
        const uint32_t* ql32 = (const uint32_t*)sQl;
        const uint32_t* kh32 = (const uint32_t*)sKh;
        const uint32_t* kl32 = (const uint32_t*)sKl;
        const int r0w = (wq * 16 + gid) * (FPAD/2);
        const int r1w = r0w + 8 * (FPAD/2);
#pragma unroll
        for (int ks = 0; ks < 4; ks++) {
            const int w = ks * 8 + tig;
            uint32_t ah[4], al[4];
            ah[0] = qh32[r0w + w];     ah[1] = qh32[r1w + w];
            ah[2] = qh32[r0w + w + 4]; ah[3] = qh32[r1w + w + 4];
            al[0] = ql32[r0w + w];     al[1] = ql32[r1w + w];
            al[2] = ql32[r0w + w + 4]; al[3] = ql32[r1w + w + 4];
#pragma unroll
            for (int nt = 0; nt < 8; nt++) {
                const int nw = (nt * 8 + gid) * (FPAD/2);
                uint32_t bh2[2] = { kh32[nw + w], kh32[nw + w + 4] };
                uint32_t bl2[2] = { kl32[nw + w], kl32[nw + w + 4] };
                mma_bf16(sc[nt], ah, bh2);
                mma_bf16(sc[nt], ah, bl2);
                mma_bf16(sc[nt], al, bh2);
            }
        }

        __syncthreads();               // all warps done reading K_t
        issueK(jn); CP_COMMIT();       // K_{t+1} loads during softmax + PV

        // ---- + PD (bf16), mask, scale ----
#pragma unroll
        for (int nt = 0; nt < 8; nt++) {
            const int jc = j0 + nt * 8 + tig * 2;
            __nv_bfloat162 p0 = *(const __nv_bfloat162*)&PDb[(size_t)s_r0 * J_ + jc];
            __nv_bfloat162 p1 = *(const __nv_bfloat162*)&PDb[(size_t)s_r1 * J_ + jc];
            sc[nt][0] = (jc     <= s_r0 + P_)
                        ? (sc[nt][0] + __bfloat162float(p0.x)) * SCALE_ : -1.0e30f;
            sc[nt][1] = (jc + 1 <= s_r0 + P_)
                        ? (sc[nt][1] + __bfloat162float(p0.y)) * SCALE_ : -1.0e30f;
            sc[nt][2] = (jc     <= s_r1 + P_)
                        ? (sc[nt][2] + __bfloat162float(p1.x)) * SCALE_ : -1.0e30f;
            sc[nt][3] = (jc + 1 <= s_r1 + P_)
                        ? (sc[nt][3] + __bfloat162float(p1.y)) * SCALE_ : -1.0e30f;
        }

        // ---- online softmax (rows r0: idx 0,1; r1: idx 2,3) ----
#pragma unroll
        for (int h = 0; h < 2; h++) {
            float mx = -3.0e38f;
#pragma unroll
            for (int nt = 0; nt < 8; nt++)
                mx = fmaxf(mx, fmaxf(sc[nt][2*h], sc[nt][2*h+1]));
            mx = fmaxf(mx, __shfl_xor_sync(0xffffffffu, mx, 1));
            mx = fmaxf(mx, __shfl_xor_sync(0xffffffffu, mx, 2));
            const float m_new = fmaxf(m_[h], mx);
            const float corr  = __expf(m_[h] - m_new);
            float sum = 0.f;
#pragma unroll
            for (int nt = 0; nt < 8; nt++) {
                float p0 = __expf(sc[nt][2*h]   - m_new);
                float p1 = __expf(sc[nt][2*h+1] - m_new);
                sc[nt][2*h] = p0; sc[nt][2*h+1] = p1;
                sum += p0 + p1;
            }
            sum += __shfl_xor_sync(0xffffffffu, sum, 1);
            sum += __shfl_xor_sync(0xffffffffu, sum, 2);
            l_[h] = l_[h] * corr + sum;
            m_[h] = m_new;
#pragma unroll
            for (int nt = 0; nt < 8; nt++) {
                o[nt][2*h]   *= corr;
                o[nt][2*h+1] *= corr;
            }
        }

        // V_t complete (all but newest 1 = K_{t+1})
        CP_WAIT1();
        __syncthreads();

        // ---- O += P @ V (P fragments from scores, V^T as B) ----
        const uint32_t* vh32 = (const uint32_t*)sVh;
        const uint32_t* vl32 = (const uint32_t*)sVl;
#pragma unroll
        for (int ks = 0; ks < 4; ks++) {
            uint32_t ph[4], pl[4];
            split2(sc[2*ks][0],   sc[2*ks][1],   ph[0], pl[0]);
            split2(sc[2*ks][2],   sc[2*ks][3],   ph[1], pl[1]);
            split2(sc[2*ks+1][0], sc[2*ks+1][1], ph[2], pl[2]);
            split2(sc[2*ks+1][2], sc[2*ks+1][3], ph[3], pl[3]);
            const int w = ks * 8 + tig;
#pragma unroll
            for (int nt = 0; nt < 8; nt++) {
                const int nw = (nt * 8 + gid) * (FPAD/2);
                uint32_t bh2[2] = { vh32[nw + w], vh32[nw + w + 4] };
                uint32_t bl2[2] = { vl32[nw + w], vl32[nw + w + 4] };
                mma_bf16(o[nt], ph, bh2);
                mma_bf16(o[nt], ph, bl2);
                mma_bf16(o[nt], pl, bh2);
            }
        }

        __syncthreads();               // all warps done reading V_t
        issueV(jn); CP_COMMIT();       // V_{t+1} loads during next scores
    }
    CP_WAIT0();   // drain outstanding (clamped) prefetches before exit

    // ---- epilogue: ctx[(s,b)][h*64+i] ----
    const float inv0 = 1.f / l_[0];
    const float inv1 = 1.f / l_[1];
    const int b = bh >> 4, hh = bh & 15;
#pragma unroll
    for (int nt = 0; nt < 8; nt++) {
        const int ic = hh * 64 + nt * 8 + tig * 2;
        *(float2*)&g_ctx[((size_t)(s_r0 * B_ + b)) * HI_ + ic] =
            make_float2(o[nt][0] * inv0, o[nt][1] * inv0);
        *(float2*)&g_ctx[((size_t)(s_r1 * B_ + b)) * HI_ + ic] =
            make_float2(o[nt][2] * inv1, o[nt][3] * inv1);
    }
}

// ------------------------------ layernorm ----------------------------------
__device__ __forceinline__ float warp_red_sum(float v) {
#pragma unroll
    for (int o = 16; o; o >>= 1) v += __shfl_xor_sync(0xffffffffu, v, o);
    return v;
}
__global__ void __launch_bounds__(256)
ln_kernel(const float* __restrict__ gamma, const float* __restrict__ beta,
          float* __restrict__ out) {
    const int row = blockIdx.x;
    const int tid = threadIdx.x;
    const float* p = g_proj + (size_t)row * E_;
    __shared__ float red[8];

    float v[4];
    float s = 0.f;
#pragma unroll
    for (int t = 0; t < 4; t++) { v[t] = p[tid + t*256]; s += v[t]; }
    s = warp_red_sum(s);
    if ((tid & 31) == 0) red[tid >> 5] = s;
    __syncthreads();
    float tot = 0.f;
#pragma unroll
    for (int w = 0; w < 8; w++) tot += red[w];
    const float mu = tot * (1.0f / E_);

    float vs = 0.f;
#pragma unroll
    for (int t = 0; t < 4; t++) { float d = v[t] - mu; vs += d * d; }
    vs = warp_red_sum(vs);
    __syncthreads();
    if ((tid & 31) == 0) red[tid >> 5] = vs;
    __syncthreads();
    float vtot = 0.f;
#pragma unroll
    for (int w = 0; w < 8; w++) vtot += red[w];
    const float inv = rsqrtf(vtot * (1.0f / E_) + EPS_);

#pragma unroll
    for (int t = 0; t < 4; t++) {
        int e = tid + t*256;
        out[(size_t)row * E_ + e] = (v[t] - mu) * inv * gamma[e] + beta[e];
    }
}

// ------------------------------- launch ------------------------------------
extern "C" void kernel_launch(void* const* d_in, const int* in_sizes, int n_in,
                              void* d_out, int out_size) {
    (void)in_sizes; (void)n_in; (void)out_size;
    const float* x     = (const float*)d_in[0];
    const float* rel   = (const float*)d_in[1];
    const float* mem   = (const float*)d_in[2];
    const float* u     = (const float*)d_in[3];
    const float* v     = (const float*)d_in[4];
    const float* Wkv   = (const float*)d_in[6];
    const float* Wq    = (const float*)d_in[7];
    const float* Wp    = (const float*)d_in[8];
    const float* Wo    = (const float*)d_in[9];
    const float* gamma = (const float*)d_in[10];
    const float* beta  = (const float*)d_in[11];
    float* out = (float*)d_out;

    // unconditional (no static guards); attribute call is capture-safe
    cudaFuncSetAttribute(flash_mma,
                         cudaFuncAttributeMaxDynamicSharedMemorySize, FLASH_SMEM);

    // 1. kv projection -> Khi/Klo, Vthi/Vtlo (split bf16, V transposed)
    gemm_mma<<<dim3(2*HI_/128, J_*B_/128, 1), 256>>>(
        ALoadKV{mem, x}, BLoadW{Wkv, E_}, CStoreKV{}, E_);

    // 2. q projection -> quhi/qulo (+u), qv fp32 (+v)
    gemm_mma<<<dim3(HI_/128, S_*B_/128, 1), 256>>>(
        ALoadPlain{x, E_}, BLoadW{Wq, E_}, CStoreQ{u, v}, E_);

    // 3. pos projection (fp32)
    gemm_mma<<<dim3(HI_/128, J_/128, 1), 256>>>(
        ALoadPlain{rel, E_}, BLoadW{Wp, E_}, CStorePos{}, E_);

    // 4. PD (pre-shifted store, bf16, tile early-exit)
    gemm_mma<<<dim3(J_/128, S_/128, B_*H_), 256>>>(
        ALoadQV{}, BLoadPos{}, CStorePD{}, I_);

    // 5. flash attention (cp.async pipelined) -> ctx
    flash_mma<<<dim3(S_/128, B_*H_), 256, FLASH_SMEM>>>();

    // 6. out projection + residual
    gemm_mma<<<dim3(E_/128, S_*B_/128, 1), 256>>>(
        ALoadCtx{}, BLoadW{Wo, HI_}, CStoreProj{x}, HI_);

    // 7. layernorm
    ln_kernel<<<S_*B_, 256>>>(gamma, beta, out);
}

// round 11
// speedup vs baseline: 1.1455x; 1.1455x over previous
#include <cuda_runtime.h>
#include <cuda_bf16.h>
#include <cstdint>

// ---------------------------------------------------------------------------
// Transformer-XL masked MHA. S=1024, P=1024, J=2048, B=2, E=1024, H=16, I=64.
// Projections: mma.sync m16n8k16 bf16, 3-term split (fp32-grade).
// PD + flash score GEMM: single-term bf16 (softmax-side, error-forgiving).
// PV: 3-term split (output-side, error-critical).
// ---------------------------------------------------------------------------

constexpr int S_   = 1024;
constexpr int P_   = 1024;
constexpr int B_   = 2;
constexpr int E_   = 1024;
constexpr int H_   = 16;
constexpr int I_   = 64;
constexpr int J_   = 2048;
constexpr int HI_  = 1024;
constexpr float SCALE_ = 0.125f;
constexpr float EPS_   = 1e-5f;

// ------------------------- scratch (device globals) ------------------------
__device__ __nv_bfloat16 g_Khi [(size_t)B_*H_*J_*I_];  // [bh][j][i]
__device__ __nv_bfloat16 g_Vthi[(size_t)B_*H_*I_*J_];  // [bh][i][j] (transposed)
__device__ __nv_bfloat16 g_Vtlo[(size_t)B_*H_*I_*J_];
__device__ __nv_bfloat16 g_quhi[(size_t)B_*H_*S_*I_];  // [bh][s][i]
__device__ __nv_bfloat16 g_qvh [(size_t)B_*H_*S_*I_];  // [bh][s][i] bf16
__device__ __nv_bfloat16 g_posh[(size_t)H_*J_*I_];     // [h][r][i]  bf16
__device__ __nv_bfloat16 g_PD  [(size_t)B_*H_*S_*J_];  // pre-shifted [bh][s][j]
__device__ float g_ctx [(size_t)S_*B_*HI_];
__device__ float g_proj[(size_t)S_*B_*E_];

// ------------------------------ helpers ------------------------------------
__device__ __forceinline__ void split1(float x, __nv_bfloat16& h, __nv_bfloat16& l) {
    h = __float2bfloat16(x);
    l = __float2bfloat16(x - __bfloat162float(h));
}
__device__ __forceinline__ void split2(float x, float y,
                                       uint32_t& hi, uint32_t& lo) {
    __nv_bfloat162 h = __floats2bfloat162_rn(x, y);
    __nv_bfloat162 l = __floats2bfloat162_rn(x - __bfloat162float(h.x),
                                             y - __bfloat162float(h.y));
    hi = *(const uint32_t*)&h;
    lo = *(const uint32_t*)&l;
}
__device__ __forceinline__ void mma_bf16(float* d, const uint32_t* a,
                                         const uint32_t* b) {
    asm volatile(
        "mma.sync.aligned.m16n8k16.row.col.f32.bf16.bf16.f32 "
        "{%0,%1,%2,%3}, {%4,%5,%6,%7}, {%8,%9}, {%0,%1,%2,%3};"
        : "+f"(d[0]), "+f"(d[1]), "+f"(d[2]), "+f"(d[3])
        : "r"(a[0]), "r"(a[1]), "r"(a[2]), "r"(a[3]), "r"(b[0]), "r"(b[1]));
}

#define CP_ASYNC16(dst_u32, src_ptr) \
    asm volatile("cp.async.cg.shared.global [%0], [%1], 16;" \
                 :: "r"(dst_u32), "l"(src_ptr) : "memory")
#define CP_COMMIT() asm volatile("cp.async.commit_group;" ::: "memory")
#define CP_WAIT1()  asm volatile("cp.async.wait_group 1;" ::: "memory")
#define CP_WAIT0()  asm volatile("cp.async.wait_group 0;" ::: "memory")

// ------------------------------- functors ----------------------------------
struct ALoadKV {
    const float* mem; const float* x;
    __device__ __forceinline__ float4 operator()(int, int m, int k) const {
        const float* p = (m < P_*B_) ? (mem + (size_t)m*E_ + k)
                                     : (x + (size_t)(m - P_*B_)*E_ + k);
        return *(const float4*)p;
    }
};
struct ALoadPlain {
    const float* a; int K;
    __device__ __forceinline__ float4 operator()(int, int m, int k) const {
        return *(const float4*)(a + (size_t)m*K + k);
    }
};
struct ALoadCtx {
    __device__ __forceinline__ float4 operator()(int, int m, int k) const {
        return *(const float4*)&g_ctx[(size_t)m*HI_ + k];
    }
};
struct BLoadW {
    const float* w; int K;
    __device__ __forceinline__ float4 operator()(int, int n, int k) const {
        return *(const float4*)(w + (size_t)n*K + k);
    }
};

struct CStoreKV {
    __device__ __forceinline__ void operator()(int, int m, int n, float c) const {
        int j = m / B_, b = m % B_;
        if (n < HI_) {
            int hh = n >> 6, i = n & 63;
            g_Khi[(((size_t)(b*H_ + hh))*J_ + j)*I_ + i] = __float2bfloat16(c);
        } else {
            int n2 = n - HI_; int hh = n2 >> 6, i = n2 & 63;
            __nv_bfloat16 h, l;
            split1(c, h, l);
            size_t o = (((size_t)(b*H_ + hh))*I_ + i)*J_ + j;  // transposed
            g_Vthi[o] = h; g_Vtlo[o] = l;
        }
    }
};
struct CStoreQ {
    const float* u; const float* v;
    __device__ __forceinline__ void operator()(int, int m, int n, float c) const {
        int s = m / B_, b = m % B_;
        int hh = n >> 6, i = n & 63;
        size_t o = (((size_t)(b*H_ + hh))*S_ + s)*I_ + i;
        g_quhi[o] = __float2bfloat16(c + u[n]);
        g_qvh[o]  = __float2bfloat16(c + v[n]);
    }
};
struct CStorePos {
    __device__ __forceinline__ void operator()(int, int m, int n, float c) const {
        int hh = n >> 6, i = n & 63;
        g_posh[((size_t)hh*J_ + m)*I_ + i] = __float2bfloat16(c);
    }
};
struct CStoreProj {
    const float* x;
    __device__ __forceinline__ void operator()(int, int m, int n, float c) const {
        g_proj[(size_t)m*E_ + n] = c + x[(size_t)m*E_ + n];
    }
};

// ------------------------- mma.sync GEMM (split-bf16) ----------------------
// Round-6 schedule: store chunk -> sync -> prefetch next -> compute -> sync.
constexpr int SROW = 40;   // bf16 elements per smem row (32 data + 8 pad)

template<class AL, class BL, class CS>
__global__ void __launch_bounds__(256)
gemm_mma(AL aload, BL bload, CS cstore, int K) {
    __shared__ __nv_bfloat16 sA[2][128 * SROW];
    __shared__ __nv_bfloat16 sB[2][128 * SROW];

    const int tid  = threadIdx.x;
    const int wid  = tid >> 5;
    const int lane = tid & 31;
    const int gid  = lane >> 2;
    const int tig  = lane & 3;
    const int wm   = wid >> 2;
    const int wn   = wid & 3;
    const int m0   = blockIdx.y * 128;
    const int n0   = blockIdx.x * 128;
    const int bz   = blockIdx.z;

    float c[4][4][4];
#pragma unroll
    for (int mt = 0; mt < 4; mt++)
#pragma unroll
        for (int nt = 0; nt < 4; nt++)
#pragma unroll
            for (int r = 0; r < 4; r++) c[mt][nt][r] = 0.f;

    float4 av[4], bv[4];
#pragma unroll
    for (int q = 0; q < 4; q++) {
        const int f = tid + q * 256, row = f >> 3, kq = (f & 7) * 4;
        av[q] = aload(bz, m0 + row, kq);
        bv[q] = bload(bz, n0 + row, kq);
    }

    for (int k0 = 0; k0 < K; k0 += 32) {
        // ---- store current chunk (split hi/lo) ----
#pragma unroll
        for (int q = 0; q < 4; q++) {
            const int f = tid + q * 256, row = f >> 3, kq = (f & 7) * 4;
            const int so = row * SROW + kq;
            uint32_t h0, l0, h1, l1;
            split2(av[q].x, av[q].y, h0, l0);
            split2(av[q].z, av[q].w, h1, l1);
            *(uint2*)&sA[0][so] = make_uint2(h0, h1);
            *(uint2*)&sA[1][so] = make_uint2(l0, l1);
            split2(bv[q].x, bv[q].y, h0, l0);
            split2(bv[q].z, bv[q].w, h1, l1);
            *(uint2*)&sB[0][so] = make_uint2(h0, h1);
            *(uint2*)&sB[1][so] = make_uint2(l0, l1);
        }
        __syncthreads();

        // ---- prefetch next chunk ----
        if (k0 + 32 < K) {
#pragma unroll
            for (int q = 0; q < 4; q++) {
                const int f = tid + q * 256, row = f >> 3, kq = (f & 7) * 4;
                av[q] = aload(bz, m0 + row, k0 + 32 + kq);
                bv[q] = bload(bz, n0 + row, k0 + 32 + kq);
            }
        }

        // ---- compute ----
#pragma unroll
        for (int ks = 0; ks < 2; ks++) {
            const int kk = ks * 16 + tig * 2;
            uint32_t ah[4][4], al[4][4];
#pragma unroll
            for (int mt = 0; mt < 4; mt++) {
                const int m = wm * 64 + mt * 16 + gid;
                ah[mt][0] = *(const uint32_t*)&sA[0][m * SROW + kk];
                ah[mt][1] = *(const uint32_t*)&sA[0][(m + 8) * SROW + kk];
                ah[mt][2] = *(const uint32_t*)&sA[0][m * SROW + kk + 8];
                ah[mt][3] = *(const uint32_t*)&sA[0][(m + 8) * SROW + kk + 8];
                al[mt][0] = *(const uint32_t*)&sA[1][m * SROW + kk];
                al[mt][1] = *(const uint32_t*)&sA[1][(m + 8) * SROW + kk];
                al[mt][2] = *(const uint32_t*)&sA[1][m * SROW + kk + 8];
                al[mt][3] = *(const uint32_t*)&sA[1][(m + 8) * SROW + kk + 8];
            }
#pragma unroll
            for (int nt = 0; nt < 4; nt++) {
                const int n = wn * 32 + nt * 8 + gid;
                uint32_t bh[2], bl[2];
                bh[0] = *(const uint32_t*)&sB[0][n * SROW + kk];
                bh[1] = *(const uint32_t*)&sB[0][n * SROW + kk + 8];
                bl[0] = *(const uint32_t*)&sB[1][n * SROW + kk];
                bl[1] = *(const uint32_t*)&sB[1][n * SROW + kk + 8];
#pragma unroll
                for (int mt = 0; mt < 4; mt++) {
                    mma_bf16(c[mt][nt], ah[mt], bh);
                    mma_bf16(c[mt][nt], ah[mt], bl);
                    mma_bf16(c[mt][nt], al[mt], bh);
                }
            }
        }
        __syncthreads();
    }

#pragma unroll
    for (int mt = 0; mt < 4; mt++) {
        const int gm = m0 + wm * 64 + mt * 16 + gid;
#pragma unroll
        for (int nt = 0; nt < 4; nt++) {
            const int gn = n0 + wn * 32 + nt * 8 + tig * 2;
            cstore(bz, gm,     gn,     c[mt][nt][0]);
            cstore(bz, gm,     gn + 1, c[mt][nt][1]);
            cstore(bz, gm + 8, gn,     c[mt][nt][2]);
            cstore(bz, gm + 8, gn + 1, c[mt][nt][3]);
        }
    }
}

// ----------------------- PD kernel (pure bf16, K=64) -----------------------
// PD[bh][s][j] = qv_s . pos_{j+1023-s}  stored pre-shifted in bf16.
// Block: 128 rows x 512 cols (4 n-subtiles of 128 sharing the smem A tile).
// grid (J/512, S/128, B*H). 8 warps, warp = 16 rows x 128 cols.
constexpr int PDW = 36;                       // words per smem row (72 bf16)
constexpr int PD_SMEM = 3 * 128 * 72 * 2;     // A + 2 B buffers = 55296 B

__global__ void __launch_bounds__(256) pd_kernel() {
    extern __shared__ __nv_bfloat16 psm[];
    __nv_bfloat16* sA  = psm;                 // [128][72]
    __nv_bfloat16* sB0 = sA  + 128 * 72;
    __nv_bfloat16* sB1 = sB0 + 128 * 72;

    const int tid  = threadIdx.x;
    const int wq   = tid >> 5;
    const int lane = tid & 31;
    const int gid  = lane >> 2;
    const int tig  = lane & 3;
    const int m0   = blockIdx.y * 128;
    const int ng   = blockIdx.x * 512;
    const int bh   = blockIdx.z;

    // first n-subtile with any j = n+m-1023 >= 0:  m0+n0 >= 769
    int ns_min = 769 - m0 - ng;
    ns_min = (ns_min <= 0) ? 0 : ((ns_min + 127) >> 7);
    if (ns_min > 3) return;

    const int arow = tid >> 1;                // 0..127
    const int aw   = (tid & 1) * 16;          // word offset (64B half-row)

    auto issueA = [&]() {
        const char* src = (const char*)((const uint32_t*)
            (g_qvh + ((size_t)bh * S_ + m0 + arow) * I_) + aw);
        uint32_t dst = (uint32_t)__cvta_generic_to_shared(
            (uint32_t*)&sA[arow * 72] + aw);
        CP_ASYNC16(dst,      src);
        CP_ASYNC16(dst + 16, src + 16);
        CP_ASYNC16(dst + 32, src + 32);
        CP_ASYNC16(dst + 48, src + 48);
    };
    auto issueB = [&](int ns, __nv_bfloat16* buf) {
        const int n0 = ng + ns * 128;
        const char* src = (const char*)((const uint32_t*)
            (g_posh + ((size_t)(bh & 15) * J_ + n0 + arow) * I_) + aw);
        uint32_t dst = (uint32_t)__cvta_generic_to_shared(
            (uint32_t*)&buf[arow * 72] + aw);
        CP_ASYNC16(dst,      src);
        CP_ASYNC16(dst + 16, src + 16);
        CP_ASYNC16(dst + 32, src + 32);
        CP_ASYNC16(dst + 48, src + 48);
    };

    issueA();
    issueB(ns_min, sB0);
    CP_COMMIT();                              // G0 = A + B[ns_min]
    if (ns_min + 1 <= 3) { issueB(ns_min + 1, sB1); CP_COMMIT(); }

    const int r0w = (wq * 16 + gid) * PDW;
    __nv_bfloat16* PDr0 = g_PD + ((size_t)bh * S_ + m0 + wq * 16 + gid) * J_;
    __nv_bfloat16* PDr1 = PDr0 + 8 * J_;
    const int gm0 = m0 + wq * 16 + gid;

    for (int ns = ns_min; ns <= 3; ns++) {
        const int idx = ns - ns_min;
        if (ns + 1 <= 3) CP_WAIT1(); else CP_WAIT0();
        __syncthreads();

        const uint32_t* qa = (const uint32_t*)sA;
        const uint32_t* qb = (const uint32_t*)((idx & 1) ? sB1 : sB0);

        float c[16][4];
#pragma unroll
        for (int nt = 0; nt < 16; nt++)
#pragma unroll
            for (int r = 0; r < 4; r++) c[nt][r] = 0.f;

#pragma unroll
        for (int ks = 0; ks < 4; ks++) {
            const int w = ks * 8 + tig;
            uint32_t a[4];
            a[0] = qa[r0w + w];
            a[1] = qa[r0w + 8 * PDW + w];
            a[2] = qa[r0w + w + 4];
            a[3] = qa[r0w + 8 * PDW + w + 4];
#pragma unroll
            for (int nt = 0; nt < 16; nt++) {
                const int nw = (nt * 8 + gid) * PDW;
                uint32_t b2[2] = { qb[nw + w], qb[nw + w + 4] };
                mma_bf16(c[nt], a, b2);
            }
        }
        __syncthreads();
        if (ns + 2 <= 3) { issueB(ns + 2, (idx & 1) ? sB1 : sB0); CP_COMMIT(); }

        // ---- store (pre-shifted j = n + m - 1023, drop j < 0) ----
        const int n0 = ng + ns * 128;
#pragma unroll
        for (int nt = 0; nt < 16; nt++) {
            const int gn  = n0 + nt * 8 + tig * 2;
            const int j0  = gn + gm0 - 1023;
            if (j0     >= 0) PDr0[j0]     = __float2bfloat16(c[nt][0]);
            if (j0 + 1 >= 0) PDr0[j0 + 1] = __float2bfloat16(c[nt][1]);
            if (j0 + 8 >= 0) PDr1[j0 + 8] = __float2bfloat16(c[nt][2]);
            if (j0 + 9 >= 0) PDr1[j0 + 9] = __float2bfloat16(c[nt][3]);
        }
    }
}

// ---------------------------- flash attention (MMA) ------------------------
// grid (S/128, B*H), 256 threads = 8 warps; warp wq owns rows wq*16..+15.
// j-tiles of 64, cp.async pipelined K/V. Scores: single-term bf16.
// PV: 3-term split (Ph*Vh + Ph*Vl + Pl*Vh).
constexpr int FPAD = 72;
constexpr int FLASH_SMEM = (128 + 64 + 128) * FPAD * 2;  // 46080 B

__global__ void __launch_bounds__(256) flash_mma() {
    extern __shared__ __nv_bfloat16 fsm[];
    __nv_bfloat16* sQh = fsm;                    // [s][i] 128x72
    __nv_bfloat16* sKh = sQh + 128 * FPAD;       // [j][i] 64x72
    __nv_bfloat16* sVh = sKh + 64 * FPAD;        // [i][j] 64x72
    __nv_bfloat16* sVl = sVh + 64 * FPAD;

    const int tid  = threadIdx.x;
    const int wq   = tid >> 5;
    const int lane = tid & 31;
    const int gid  = lane >> 2;
    const int tig  = lane & 3;
    // heavy s-blocks launch first
    const int s0   = (gridDim.x - 1 - blockIdx.x) * 128;
    const int bh   = blockIdx.y;

    const int s_r0 = s0 + wq * 16 + gid;
    const int s_r1 = s_r0 + 8;

    const int row4 = tid >> 2;            // 0..63
    const int qw   = (tid & 3) * 8;       // word offset

    auto issueK = [&](int j0) {
        const char* srch = (const char*)((const uint32_t*)
            (g_Khi + (((size_t)bh * J_) + j0 + row4) * I_) + qw);
        uint32_t dh = (uint32_t)__cvta_generic_to_shared(
            (uint32_t*)&sKh[row4 * FPAD] + qw);
        CP_ASYNC16(dh,      srch);
        CP_ASYNC16(dh + 16, srch + 16);
    };
    auto issueV = [&](int j0) {
        const char* srch = (const char*)((const uint32_t*)
            (g_Vthi + ((size_t)bh * I_ + row4) * J_ + j0) + qw);
        const char* srcl = (const char*)((const uint32_t*)
            (g_Vtlo + ((size_t)bh * I_ + row4) * J_ + j0) + qw);
        uint32_t dh = (uint32_t)__cvta_generic_to_shared(
            (uint32_t*)&sVh[row4 * FPAD] + qw);
        uint32_t dl = (uint32_t)__cvta_generic_to_shared(
            (uint32_t*)&sVl[row4 * FPAD] + qw);
        CP_ASYNC16(dh,      srch);
        CP_ASYNC16(dh + 16, srch + 16);
        CP_ASYNC16(dl,      srcl);
        CP_ASYNC16(dl + 16, srcl + 16);
    };

    issueK(0); CP_COMMIT();
    issueV(0); CP_COMMIT();

    // ---- load Q tile (hi only) ----
    {
        const int row  = tid >> 1;
        const int half = (tid & 1) * 16;
        const uint4* srch = (const uint4*)((const uint32_t*)
            (g_quhi + ((size_t)bh * S_ + s0 + row) * I_) + half);
        uint4* dsth = (uint4*)((uint32_t*)&sQh[row * FPAD] + half);
#pragma unroll
        for (int q = 0; q < 4; q++) dsth[q] = srch[q];
    }

    const __nv_bfloat16* PDb = g_PD + (size_t)bh * S_ * J_;

    float m_[2] = {-3.0e38f, -3.0e38f};
    float l_[2] = {0.f, 0.f};
    float o[8][4];
#pragma unroll
    for (int nt = 0; nt < 8; nt++)
#pragma unroll
        for (int r = 0; r < 4; r++) o[nt][r] = 0.f;

    const int ntiles = min(32, s0 / 64 + 18);
    for (int jt = 0; jt < ntiles; jt++) {
        const int j0 = jt * 64;
        const int jn = min(jt + 1, ntiles - 1) * 64;   // clamped prefetch

        CP_WAIT1();
        __syncthreads();

        // ---- scores S = Q @ K^T (single-term bf16) ----
        float sc[8][4];
#pragma unroll
        for (int nt = 0; nt < 8; nt++)
#pragma unroll
            for (int r = 0; r < 4; r++) sc[nt][r] = 0.f;

        const uint32_t* qh32 = (const uint32_t*)sQh;
        const uint32_t* kh32 = (const uint32_t*)sKh;
        const int r0w = (wq * 16 + gid) * (FPAD/2);
        const int r1w = r0w + 8 * (FPAD/2);
#pragma unroll
        for (int ks = 0; ks < 4; ks++) {
            const int w = ks * 8 + tig;
            uint32_t ah[4];
            ah[0] = qh32[r0w + w];     ah[1] = qh32[r1w + w];
            ah[2] = qh32[r0w + w + 4]; ah[3] = qh32[r1w + w + 4];
#pragma unroll
            for (int nt = 0; nt < 8; nt++) {
                const int nw = (nt * 8 + gid) * (FPAD/2);
                uint32_t bh2[2] = { kh32[nw + w], kh32[nw + w + 4] };
                mma_bf16(sc[nt], ah, bh2);
            }
        }

        __syncthreads();               // all warps done reading K_t
        issueK(jn); CP_COMMIT();       // K_{t+1} loads during softmax + PV

        // ---- + PD (bf16), mask, scale ----
#pragma unroll
        for (int nt = 0; nt < 8; nt++) {
            const int jc = j0 + nt * 8 + tig * 2;
            __nv_bfloat162 p0 = *(const __nv_bfloat162*)&PDb[(size_t)s_r0 * J_ + jc];
            __nv_bfloat162 p1 = *(const __nv_bfloat162*)&PDb[(size_t)s_r1 * J_ + jc];
            sc[nt][0] = (jc     <= s_r0 + P_)
                        ? (sc[nt][0] + __bfloat162float(p0.x)) * SCALE_ : -1.0e30f;
            sc[nt][1] = (jc + 1 <= s_r0 + P_)
                        ? (sc[nt][1] + __bfloat162float(p0.y)) * SCALE_ : -1.0e30f;
            sc[nt][2] = (jc     <= s_r1 + P_)
                        ? (sc[nt][2] + __bfloat162float(p1.x)) * SCALE_ : -1.0e30f;
            sc[nt][3] = (jc + 1 <= s_r1 + P_)
                        ? (sc[nt][3] + __bfloat162float(p1.y)) * SCALE_ : -1.0e30f;
        }

        // ---- online softmax ----
#pragma unroll
        for (int h = 0; h < 2; h++) {
            float mx = -3.0e38f;
#pragma unroll
            for (int nt = 0; nt < 8; nt++)
                mx = fmaxf(mx, fmaxf(sc[nt][2*h], sc[nt][2*h+1]));
            mx = fmaxf(mx, __shfl_xor_sync(0xffffffffu, mx, 1));
            mx = fmaxf(mx, __shfl_xor_sync(0xffffffffu, mx, 2));
            const float m_new = fmaxf(m_[h], mx);
            const float corr  = __expf(m_[h] - m_new);
            float sum = 0.f;
#pragma unroll
            for (int nt = 0; nt < 8; nt++) {
                float p0 = __expf(sc[nt][2*h]   - m_new);
                float p1 = __expf(sc[nt][2*h+1] - m_new);
                sc[nt][2*h] = p0; sc[nt][2*h+1] = p1;
                sum += p0 + p1;
            }
            sum += __shfl_xor_sync(0xffffffffu, sum, 1);
            sum += __shfl_xor_sync(0xffffffffu, sum, 2);
            l_[h] = l_[h] * corr + sum;
            m_[h] = m_new;
#pragma unroll
            for (int nt = 0; nt < 8; nt++) {
                o[nt][2*h]   *= corr;
                o[nt][2*h+1] *= corr;
            }
        }

        CP_WAIT1();
        __syncthreads();

        // ---- O += P @ V (3-term split) ----
        const uint32_t* vh32 = (const uint32_t*)sVh;
        const uint32_t* vl32 = (const uint32_t*)sVl;
#pragma unroll
        for (int ks = 0; ks < 4; ks++) {
            uint32_t ph[4], pl[4];
            split2(sc[2*ks][0],   sc[2*ks][1],   ph[0], pl[0]);
            split2(sc[2*ks][2],   sc[2*ks][3],   ph[1], pl[1]);
            split2(sc[2*ks+1][0], sc[2*ks+1][1], ph[2], pl[2]);
            split2(sc[2*ks+1][2], sc[2*ks+1][3], ph[3], pl[3]);
            const int w = ks * 8 + tig;
#pragma unroll
            for (int nt = 0; nt < 8; nt++) {
                const int nw = (nt * 8 + gid) * (FPAD/2);
                uint32_t bh2[2] = { vh32[nw + w], vh32[nw + w + 4] };
                uint32_t bl2[2] = { vl32[nw + w], vl32[nw + w + 4] };
                mma_bf16(o[nt], ph, bh2);
                mma_bf16(o[nt], ph, bl2);
                mma_bf16(o[nt], pl, bh2);
            }
        }

        __syncthreads();
        issueV(jn); CP_COMMIT();       // V_{t+1} loads during next scores
    }
    CP_WAIT0();

    // ---- epilogue: ctx[(s,b)][h*64+i] ----
    const float inv0 = 1.f / l_[0];
    const float inv1 = 1.f / l_[1];
    const int b = bh >> 4, hh = bh & 15;
#pragma unroll
    for (int nt = 0; nt < 8; nt++) {
        const int ic = hh * 64 + nt * 8 + tig * 2;
        *(float2*)&g_ctx[((size_t)(s_r0 * B_ + b)) * HI_ + ic] =
            make_float2(o[nt][0] * inv0, o[nt][1] * inv0);
        *(float2*)&g_ctx[((size_t)(s_r1 * B_ + b)) * HI_ + ic] =
            make_float2(o[nt][2] * inv1, o[nt][3] * inv1);
    }
}

// ------------------------------ layernorm ----------------------------------
__device__ __forceinline__ float warp_red_sum(float v) {
#pragma unroll
    for (int o = 16; o; o >>= 1) v += __shfl_xor_sync(0xffffffffu, v, o);
    return v;
}
__global__ void __launch_bounds__(256)
ln_kernel(const float* __restrict__ gamma, const float* __restrict__ beta,
          float* __restrict__ out) {
    const int row = blockIdx.x;
    const int tid = threadIdx.x;
    const float* p = g_proj + (size_t)row * E_;
    __shared__ float red[8];

    float v[4];
    float s = 0.f;
#pragma unroll
    for (int t = 0; t < 4; t++) { v[t] = p[tid + t*256]; s += v[t]; }
    s = warp_red_sum(s);
    if ((tid & 31) == 0) red[tid >> 5] = s;
    __syncthreads();
    float tot = 0.f;
#pragma unroll
    for (int w = 0; w < 8; w++) tot += red[w];
    const float mu = tot * (1.0f / E_);

    float vs = 0.f;
#pragma unroll
    for (int t = 0; t < 4; t++) { float d = v[t] - mu; vs += d * d; }
    vs = warp_red_sum(vs);
    __syncthreads();
    if ((tid & 31) == 0) red[tid >> 5] = vs;
    __syncthreads();
    float vtot = 0.f;
#pragma unroll
    for (int w = 0; w < 8; w++) vtot += red[w];
    const float inv = rsqrtf(vtot * (1.0f / E_) + EPS_);

#pragma unroll
    for (int t = 0; t < 4; t++) {
        int e = tid + t*256;
        out[(size_t)row * E_ + e] = (v[t] - mu) * inv * gamma[e] + beta[e];
    }
}

// ------------------------------- launch ------------------------------------
extern "C" void kernel_launch(void* const* d_in, const int* in_sizes, int n_in,
                              void* d_out, int out_size) {
    (void)in_sizes; (void)n_in; (void)out_size;
    const float* x     = (const float*)d_in[0];
    const float* rel   = (const float*)d_in[1];
    const float* mem   = (const float*)d_in[2];
    const float* u     = (const float*)d_in[3];
    const float* v     = (const float*)d_in[4];
    const float* Wkv   = (const float*)d_in[6];
    const float* Wq    = (const float*)d_in[7];
    const float* Wp    = (const float*)d_in[8];
    const float* Wo    = (const float*)d_in[9];
    const float* gamma = (const float*)d_in[10];
    const float* beta  = (const float*)d_in[11];
    float* out = (float*)d_out;

    // unconditional (no static guards); attribute calls are capture-safe
    cudaFuncSetAttribute(flash_mma,
                         cudaFuncAttributeMaxDynamicSharedMemorySize, FLASH_SMEM);
    cudaFuncSetAttribute(pd_kernel,
                         cudaFuncAttributeMaxDynamicSharedMemorySize, PD_SMEM);

    // 1. kv projection -> Khi (bf16), Vthi/Vtlo (split bf16, transposed)
    gemm_mma<<<dim3(2*HI_/128, J_*B_/128, 1), 256>>>(
        ALoadKV{mem, x}, BLoadW{Wkv, E_}, CStoreKV{}, E_);

    // 2. q projection -> quhi (+u), qvh (+v), both bf16
    gemm_mma<<<dim3(HI_/128, S_*B_/128, 1), 256>>>(
        ALoadPlain{x, E_}, BLoadW{Wq, E_}, CStoreQ{u, v}, E_);

    // 3. pos projection -> posh (bf16)
    gemm_mma<<<dim3(HI_/128, J_/128, 1), 256>>>(
        ALoadPlain{rel, E_}, BLoadW{Wp, E_}, CStorePos{}, E_);

    // 4. PD (dedicated bf16 kernel, pre-shifted store, subtile early-exit)
    pd_kernel<<<dim3(J_/512, S_/128, B_*H_), 256, PD_SMEM>>>();

    // 5. flash attention -> ctx
    flash_mma<<<dim3(S_/128, B_*H_), 256, FLASH_SMEM>>>();

    // 6. out projection + residual
    gemm_mma<<<dim3(E_/128, S_*B_/128, 1), 256>>>(
        ALoadCtx{}, BLoadW{Wo, HI_}, CStoreProj{x}, HI_);

    // 7. layernorm
    ln_kernel<<<S_*B_, 256>>>(gamma, beta, out);
}

// round 12
// speedup vs baseline: 1.2228x; 1.0675x over previous
#include <cuda_runtime.h>
#include <cuda_bf16.h>
#include <cstdint>

// ---------------------------------------------------------------------------
// Transformer-XL masked MHA. S=1024, P=1024, J=2048, B=2, E=1024, H=16, I=64.
// Projections: mma.sync m16n8k16 bf16, 3-term split (fp32-grade).
// PD + flash score GEMM: single-term bf16 (softmax-side, error-forgiving).
// PV: 3-term split (output-side, error-critical).
// ---------------------------------------------------------------------------

constexpr int S_   = 1024;
constexpr int P_   = 1024;
constexpr int B_   = 2;
constexpr int E_   = 1024;
constexpr int H_   = 16;
constexpr int I_   = 64;
constexpr int J_   = 2048;
constexpr int HI_  = 1024;
constexpr float SCALE_ = 0.125f;
constexpr float EPS_   = 1e-5f;

// ------------------------- scratch (device globals) ------------------------
__device__ __nv_bfloat16 g_Khi [(size_t)B_*H_*J_*I_];  // [bh][j][i]
__device__ __nv_bfloat16 g_Vthi[(size_t)B_*H_*I_*J_];  // [bh][i][j] (transposed)
__device__ __nv_bfloat16 g_Vtlo[(size_t)B_*H_*I_*J_];
__device__ __nv_bfloat16 g_quhi[(size_t)B_*H_*S_*I_];  // [bh][s][i]
__device__ __nv_bfloat16 g_qvh [(size_t)B_*H_*S_*I_];  // [bh][s][i] bf16
__device__ __nv_bfloat16 g_posh[(size_t)H_*J_*I_];     // [h][r][i]  bf16
__device__ __nv_bfloat16 g_PD  [(size_t)B_*H_*S_*J_];  // pre-shifted [bh][s][j]
__device__ float g_ctx [(size_t)S_*B_*HI_];
__device__ float g_proj[(size_t)S_*B_*E_];

// ------------------------------ helpers ------------------------------------
__device__ __forceinline__ void split1(float x, __nv_bfloat16& h, __nv_bfloat16& l) {
    h = __float2bfloat16(x);
    l = __float2bfloat16(x - __bfloat162float(h));
}
__device__ __forceinline__ void split2(float x, float y,
                                       uint32_t& hi, uint32_t& lo) {
    __nv_bfloat162 h = __floats2bfloat162_rn(x, y);
    __nv_bfloat162 l = __floats2bfloat162_rn(x - __bfloat162float(h.x),
                                             y - __bfloat162float(h.y));
    hi = *(const uint32_t*)&h;
    lo = *(const uint32_t*)&l;
}
__device__ __forceinline__ uint32_t packbf2(float x, float y) {
    __nv_bfloat162 t = __floats2bfloat162_rn(x, y);
    return *(const uint32_t*)&t;
}
__device__ __forceinline__ void mma_bf16(float* d, const uint32_t* a,
                                         const uint32_t* b) {
    asm volatile(
        "mma.sync.aligned.m16n8k16.row.col.f32.bf16.bf16.f32 "
        "{%0,%1,%2,%3}, {%4,%5,%6,%7}, {%8,%9}, {%0,%1,%2,%3};"
        : "+f"(d[0]), "+f"(d[1]), "+f"(d[2]), "+f"(d[3])
        : "r"(a[0]), "r"(a[1]), "r"(a[2]), "r"(a[3]), "r"(b[0]), "r"(b[1]));
}

#define CP_ASYNC16(dst_u32, src_ptr) \
    asm volatile("cp.async.cg.shared.global [%0], [%1], 16;" \
                 :: "r"(dst_u32), "l"(src_ptr) : "memory")
#define CP_COMMIT() asm volatile("cp.async.commit_group;" ::: "memory")
#define CP_WAIT1()  asm volatile("cp.async.wait_group 1;" ::: "memory")
#define CP_WAIT0()  asm volatile("cp.async.wait_group 0;" ::: "memory")

// ------------------------------- functors ----------------------------------
struct ALoadKV {
    const float* mem; const float* x;
    __device__ __forceinline__ float4 operator()(int, int m, int k) const {
        const float* p = (m < P_*B_) ? (mem + (size_t)m*E_ + k)
                                     : (x + (size_t)(m - P_*B_)*E_ + k);
        return *(const float4*)p;
    }
};
struct ALoadPlain {
    const float* a; int K;
    __device__ __forceinline__ float4 operator()(int, int m, int k) const {
        return *(const float4*)(a + (size_t)m*K + k);
    }
};
struct ALoadCtx {
    __device__ __forceinline__ float4 operator()(int, int m, int k) const {
        return *(const float4*)&g_ctx[(size_t)m*HI_ + k];
    }
};
struct BLoadW {
    const float* w; int K;
    __device__ __forceinline__ float4 operator()(int, int n, int k) const {
        return *(const float4*)(w + (size_t)n*K + k);
    }
};

struct CStoreKV {
    __device__ __forceinline__ void operator()(int, int m, int n, float c) const {
        int j = m / B_, b = m % B_;
        if (n < HI_) {
            int hh = n >> 6, i = n & 63;
            g_Khi[(((size_t)(b*H_ + hh))*J_ + j)*I_ + i] = __float2bfloat16(c);
        } else {
            int n2 = n - HI_; int hh = n2 >> 6, i = n2 & 63;
            __nv_bfloat16 h, l;
            split1(c, h, l);
            size_t o = (((size_t)(b*H_ + hh))*I_ + i)*J_ + j;  // transposed
            g_Vthi[o] = h; g_Vtlo[o] = l;
        }
    }
};
struct CStoreQ {
    const float* u; const float* v;
    __device__ __forceinline__ void operator()(int, int m, int n, float c) const {
        int s = m / B_, b = m % B_;
        int hh = n >> 6, i = n & 63;
        size_t o = (((size_t)(b*H_ + hh))*S_ + s)*I_ + i;
        g_quhi[o] = __float2bfloat16(c + u[n]);
        g_qvh[o]  = __float2bfloat16(c + v[n]);
    }
};
struct CStorePos {
    __device__ __forceinline__ void operator()(int, int m, int n, float c) const {
        int hh = n >> 6, i = n & 63;
        g_posh[((size_t)hh*J_ + m)*I_ + i] = __float2bfloat16(c);
    }
};
struct CStoreProj {
    const float* x;
    __device__ __forceinline__ void operator()(int, int m, int n, float c) const {
        g_proj[(size_t)m*E_ + n] = c + x[(size_t)m*E_ + n];
    }
};

// ------------------------- mma.sync GEMM (split-bf16) ----------------------
// Round-6 schedule: store chunk -> sync -> prefetch next -> compute -> sync.
constexpr int SROW = 40;   // bf16 elements per smem row (32 data + 8 pad)

template<class AL, class BL, class CS>
__global__ void __launch_bounds__(256)
gemm_mma(AL aload, BL bload, CS cstore, int K) {
    __shared__ __nv_bfloat16 sA[2][128 * SROW];
    __shared__ __nv_bfloat16 sB[2][128 * SROW];

    const int tid  = threadIdx.x;
    const int wid  = tid >> 5;
    const int lane = tid & 31;
    const int gid  = lane >> 2;
    const int tig  = lane & 3;
    const int wm   = wid >> 2;
    const int wn   = wid & 3;
    const int m0   = blockIdx.y * 128;
    const int n0   = blockIdx.x * 128;
    const int bz   = blockIdx.z;

    float c[4][4][4];
#pragma unroll
    for (int mt = 0; mt < 4; mt++)
#pragma unroll
        for (int nt = 0; nt < 4; nt++)
#pragma unroll
            for (int r = 0; r < 4; r++) c[mt][nt][r] = 0.f;

    float4 av[4], bv[4];
#pragma unroll
    for (int q = 0; q < 4; q++) {
        const int f = tid + q * 256, row = f >> 3, kq = (f & 7) * 4;
        av[q] = aload(bz, m0 + row, kq);
        bv[q] = bload(bz, n0 + row, kq);
    }

    for (int k0 = 0; k0 < K; k0 += 32) {
        // ---- store current chunk (split hi/lo) ----
#pragma unroll
        for (int q = 0; q < 4; q++) {
            const int f = tid + q * 256, row = f >> 3, kq = (f & 7) * 4;
            const int so = row * SROW + kq;
            uint32_t h0, l0, h1, l1;
            split2(av[q].x, av[q].y, h0, l0);
            split2(av[q].z, av[q].w, h1, l1);
            *(uint2*)&sA[0][so] = make_uint2(h0, h1);
            *(uint2*)&sA[1][so] = make_uint2(l0, l1);
            split2(bv[q].x, bv[q].y, h0, l0);
            split2(bv[q].z, bv[q].w, h1, l1);
            *(uint2*)&sB[0][so] = make_uint2(h0, h1);
            *(uint2*)&sB[1][so] = make_uint2(l0, l1);
        }
        __syncthreads();

        // ---- prefetch next chunk ----
        if (k0 + 32 < K) {
#pragma unroll
            for (int q = 0; q < 4; q++) {
                const int f = tid + q * 256, row = f >> 3, kq = (f & 7) * 4;
                av[q] = aload(bz, m0 + row, k0 + 32 + kq);
                bv[q] = bload(bz, n0 + row, k0 + 32 + kq);
            }
        }

        // ---- compute ----
#pragma unroll
        for (int ks = 0; ks < 2; ks++) {
            const int kk = ks * 16 + tig * 2;
            uint32_t ah[4][4], al[4][4];
#pragma unroll
            for (int mt = 0; mt < 4; mt++) {
                const int m = wm * 64 + mt * 16 + gid;
                ah[mt][0] = *(const uint32_t*)&sA[0][m * SROW + kk];
                ah[mt][1] = *(const uint32_t*)&sA[0][(m + 8) * SROW + kk];
                ah[mt][2] = *(const uint32_t*)&sA[0][m * SROW + kk + 8];
                ah[mt][3] = *(const uint32_t*)&sA[0][(m + 8) * SROW + kk + 8];
                al[mt][0] = *(const uint32_t*)&sA[1][m * SROW + kk];
                al[mt][1] = *(const uint32_t*)&sA[1][(m + 8) * SROW + kk];
                al[mt][2] = *(const uint32_t*)&sA[1][m * SROW + kk + 8];
                al[mt][3] = *(const uint32_t*)&sA[1][(m + 8) * SROW + kk + 8];
            }
#pragma unroll
            for (int nt = 0; nt < 4; nt++) {
                const int n = wn * 32 + nt * 8 + gid;
                uint32_t bh[2], bl[2];
                bh[0] = *(const uint32_t*)&sB[0][n * SROW + kk];
                bh[1] = *(const uint32_t*)&sB[0][n * SROW + kk + 8];
                bl[0] = *(const uint32_t*)&sB[1][n * SROW + kk];
                bl[1] = *(const uint32_t*)&sB[1][n * SROW + kk + 8];
#pragma unroll
                for (int mt = 0; mt < 4; mt++) {
                    mma_bf16(c[mt][nt], ah[mt], bh);
                    mma_bf16(c[mt][nt], ah[mt], bl);
                    mma_bf16(c[mt][nt], al[mt], bh);
                }
            }
        }
        __syncthreads();
    }

#pragma unroll
    for (int mt = 0; mt < 4; mt++) {
        const int gm = m0 + wm * 64 + mt * 16 + gid;
#pragma unroll
        for (int nt = 0; nt < 4; nt++) {
            const int gn = n0 + wn * 32 + nt * 8 + tig * 2;
            cstore(bz, gm,     gn,     c[mt][nt][0]);
            cstore(bz, gm,     gn + 1, c[mt][nt][1]);
            cstore(bz, gm + 8, gn,     c[mt][nt][2]);
            cstore(bz, gm + 8, gn + 1, c[mt][nt][3]);
        }
    }
}

// ----------------------- PD kernel v2 (pure bf16, K=64) --------------------
// PD[bh][s][j] = qv_s . pos_{j+1023-s}  stored pre-shifted in bf16.
// Block: 128 rows x 256 cols (4 n-subtiles of 64 sharing the smem A tile).
// grid (J/256, S/128, B*H) = (8, 8, 32). 8 warps, warp = 16 rows x 64 cols.
// c[8][4] = 32 accum regs -> ~64 regs total -> 3-4 CTAs/SM.
constexpr int PDW = 36;                       // words per smem row (72 bf16)
constexpr int PD_SMEM = (128 + 2 * 64) * 72 * 2;   // A + 2 B bufs = 36864 B

__global__ void __launch_bounds__(256) pd_kernel() {
    extern __shared__ __nv_bfloat16 psm[];
    __nv_bfloat16* sA  = psm;                 // [128][72]
    __nv_bfloat16* sB0 = sA  + 128 * 72;      // [64][72]
    __nv_bfloat16* sB1 = sB0 + 64 * 72;

    const int tid  = threadIdx.x;
    const int wq   = tid >> 5;
    const int lane = tid & 31;
    const int gid  = lane >> 2;
    const int tig  = lane & 3;
    const int m0   = blockIdx.y * 128;
    const int ng   = blockIdx.x * 256;
    const int bh   = blockIdx.z;

    // subtile ns has a valid element iff m0+127 + (ng+ns*64)+63 >= 1023
    int need = 833 - m0 - ng;
    int ns_min = (need <= 0) ? 0 : ((need + 63) >> 6);
    if (ns_min > 3) return;

    // A fill: 128 rows x 128B, 2 threads/row (64B each)
    const int arow = tid >> 1;
    const int aw   = (tid & 1) * 16;          // word offset
    // B fill: 64 rows x 128B, 4 threads/row (32B each)
    const int brow = tid >> 2;
    const int bw   = (tid & 3) * 8;           // word offset

    auto issueA = [&]() {
        const char* src = (const char*)((const uint32_t*)
            (g_qvh + ((size_t)bh * S_ + m0 + arow) * I_) + aw);
        uint32_t dst = (uint32_t)__cvta_generic_to_shared(
            (uint32_t*)&sA[arow * 72] + aw);
        CP_ASYNC16(dst,      src);
        CP_ASYNC16(dst + 16, src + 16);
        CP_ASYNC16(dst + 32, src + 32);
        CP_ASYNC16(dst + 48, src + 48);
    };
    auto issueB = [&](int ns, __nv_bfloat16* buf) {
        const int n0 = ng + ns * 64;
        const char* src = (const char*)((const uint32_t*)
            (g_posh + ((size_t)(bh & 15) * J_ + n0 + brow) * I_) + bw);
        uint32_t dst = (uint32_t)__cvta_generic_to_shared(
            (uint32_t*)&buf[brow * 72] + bw);
        CP_ASYNC16(dst,      src);
        CP_ASYNC16(dst + 16, src + 16);
    };

    issueA();
    issueB(ns_min, sB0);
    CP_COMMIT();                              // G0 = A + B[ns_min]
    if (ns_min + 1 <= 3) { issueB(ns_min + 1, sB1); CP_COMMIT(); }

    const int r0w = (wq * 16 + gid) * PDW;
    const int gm0 = m0 + wq * 16 + gid;
    __nv_bfloat16* PDr0 = g_PD + ((size_t)bh * S_ + gm0) * J_;
    __nv_bfloat16* PDr1 = PDr0 + 8 * J_;
    const bool aligned = (gm0 & 1);           // gn even + gm0 odd -> j0 even

    for (int ns = ns_min; ns <= 3; ns++) {
        const int idx = ns - ns_min;
        if (ns + 1 <= 3) CP_WAIT1(); else CP_WAIT0();
        __syncthreads();

        const uint32_t* qa = (const uint32_t*)sA;
        const uint32_t* qb = (const uint32_t*)((idx & 1) ? sB1 : sB0);

        float c[8][4];
#pragma unroll
        for (int nt = 0; nt < 8; nt++)
#pragma unroll
            for (int r = 0; r < 4; r++) c[nt][r] = 0.f;

#pragma unroll
        for (int ks = 0; ks < 4; ks++) {
            const int w = ks * 8 + tig;
            uint32_t a[4];
            a[0] = qa[r0w + w];
            a[1] = qa[r0w + 8 * PDW + w];
            a[2] = qa[r0w + w + 4];
            a[3] = qa[r0w + 8 * PDW + w + 4];
#pragma unroll
            for (int nt = 0; nt < 8; nt++) {
                const int nw = (nt * 8 + gid) * PDW;
                uint32_t b2[2] = { qb[nw + w], qb[nw + w + 4] };
                mma_bf16(c[nt], a, b2);
            }
        }
        __syncthreads();
        if (ns + 2 <= 3) { issueB(ns + 2, (idx & 1) ? sB1 : sB0); CP_COMMIT(); }

        // ---- store (pre-shifted j = n + m - 1023, drop j < 0) ----
        const int n0 = ng + ns * 64;
        if (aligned) {
            // j0 even: bf16x2 pairs, all-or-nothing validity
#pragma unroll
            for (int nt = 0; nt < 8; nt++) {
                const int gn = n0 + nt * 8 + tig * 2;
                const int j0 = gn + gm0 - 1023;
                if (j0 >= 0)
                    *(uint32_t*)&PDr0[j0] = packbf2(c[nt][0], c[nt][1]);
                if (j0 + 8 >= 0)
                    *(uint32_t*)&PDr1[j0 + 8] = packbf2(c[nt][2], c[nt][3]);
            }
        } else {
#pragma unroll
            for (int nt = 0; nt < 8; nt++) {
                const int gn = n0 + nt * 8 + tig * 2;
                const int j0 = gn + gm0 - 1023;
                if (j0     >= 0) PDr0[j0]     = __float2bfloat16(c[nt][0]);
                if (j0 + 1 >= 0) PDr0[j0 + 1] = __float2bfloat16(c[nt][1]);
                if (j0 + 8 >= 0) PDr1[j0 + 8] = __float2bfloat16(c[nt][2]);
                if (j0 + 9 >= 0) PDr1[j0 + 9] = __float2bfloat16(c[nt][3]);
            }
        }
    }
}

// ---------------------------- flash attention (MMA) ------------------------
// grid (S/128, B*H), 256 threads = 8 warps; warp wq owns rows wq*16..+15.
// j-tiles of 64, cp.async pipelined K/V. Scores: single-term bf16.
// PV: 3-term split (Ph*Vh + Ph*Vl + Pl*Vh).
constexpr int FPAD = 72;
constexpr int FLASH_SMEM = (128 + 64 + 128) * FPAD * 2;  // 46080 B

__global__ void __launch_bounds__(256) flash_mma() {
    extern __shared__ __nv_bfloat16 fsm[];
    __nv_bfloat16* sQh = fsm;                    // [s][i] 128x72
    __nv_bfloat16* sKh = sQh + 128 * FPAD;       // [j][i] 64x72
    __nv_bfloat16* sVh = sKh + 64 * FPAD;        // [i][j] 64x72
    __nv_bfloat16* sVl = sVh + 64 * FPAD;

    const int tid  = threadIdx.x;
    const int wq   = tid >> 5;
    const int lane = tid & 31;
    const int gid  = lane >> 2;
    const int tig  = lane & 3;
    // heavy s-blocks launch first
    const int s0   = (gridDim.x - 1 - blockIdx.x) * 128;
    const int bh   = blockIdx.y;

    const int s_r0 = s0 + wq * 16 + gid;
    const int s_r1 = s_r0 + 8;

    const int row4 = tid >> 2;            // 0..63
    const int qw   = (tid & 3) * 8;       // word offset

    auto issueK = [&](int j0) {
        const char* srch = (const char*)((const uint32_t*)
            (g_Khi + (((size_t)bh * J_) + j0 + row4) * I_) + qw);
        uint32_t dh = (uint32_t)__cvta_generic_to_shared(
            (uint32_t*)&sKh[row4 * FPAD] + qw);
        CP_ASYNC16(dh,      srch);
        CP_ASYNC16(dh + 16, srch + 16);
    };
    auto issueV = [&](int j0) {
        const char* srch = (const char*)((const uint32_t*)
            (g_Vthi + ((size_t)bh * I_ + row4) * J_ + j0) + qw);
        const char* srcl = (const char*)((const uint32_t*)
            (g_Vtlo + ((size_t)bh * I_ + row4) * J_ + j0) + qw);
        uint32_t dh = (uint32_t)__cvta_generic_to_shared(
            (uint32_t*)&sVh[row4 * FPAD] + qw);
        uint32_t dl = (uint32_t)__cvta_generic_to_shared(
            (uint32_t*)&sVl[row4 * FPAD] + qw);
        CP_ASYNC16(dh,      srch);
        CP_ASYNC16(dh + 16, srch + 16);
        CP_ASYNC16(dl,      srcl);
        CP_ASYNC16(dl + 16, srcl + 16);
    };

    issueK(0); CP_COMMIT();
    issueV(0); CP_COMMIT();

    // ---- load Q tile (hi only) ----
    {
        const int row  = tid >> 1;
        const int half = (tid & 1) * 16;
        const uint4* srch = (const uint4*)((const uint32_t*)
            (g_quhi + ((size_t)bh * S_ + s0 + row) * I_) + half);
        uint4* dsth = (uint4*)((uint32_t*)&sQh[row * FPAD] + half);
#pragma unroll
        for (int q = 0; q < 4; q++) dsth[q] = srch[q];
    }

    const __nv_bfloat16* PDb = g_PD + (size_t)bh * S_ * J_;

    float m_[2] = {-3.0e38f, -3.0e38f};
    float l_[2] = {0.f, 0.f};
    float o[8][4];
#pragma unroll
    for (int nt = 0; nt < 8; nt++)
#pragma unroll
        for (int r = 0; r < 4; r++) o[nt][r] = 0.f;

    const int ntiles = min(32, s0 / 64 + 18);
    for (int jt = 0; jt < ntiles; jt++) {
        const int j0 = jt * 64;
        const int jn = min(jt + 1, ntiles - 1) * 64;   // clamped prefetch

        CP_WAIT1();
        __syncthreads();

        // ---- scores S = Q @ K^T (single-term bf16) ----
        float sc[8][4];
#pragma unroll
        for (int nt = 0; nt < 8; nt++)
#pragma unroll
            for (int r = 0; r < 4; r++) sc[nt][r] = 0.f;

        const uint32_t* qh32 = (const uint32_t*)sQh;
        const uint32_t* kh32 = (const uint32_t*)sKh;
        const int r0w = (wq * 16 + gid) * (FPAD/2);
        const int r1w = r0w + 8 * (FPAD/2);
#pragma unroll
        for (int ks = 0; ks < 4; ks++) {
            const int w = ks * 8 + tig;
            uint32_t ah[4];
            ah[0] = qh32[r0w + w];     ah[1] = qh32[r1w + w];
            ah[2] = qh32[r0w + w + 4]; ah[3] = qh32[r1w + w + 4];
#pragma unroll
            for (int nt = 0; nt < 8; nt++) {
                const int nw = (nt * 8 + gid) * (FPAD/2);
                uint32_t bh2[2] = { kh32[nw + w], kh32[nw + w + 4] };
                mma_bf16(sc[nt], ah, bh2);
            }
        }

        __syncthreads();               // all warps done reading K_t
        issueK(jn); CP_COMMIT();       // K_{t+1} loads during softmax + PV

        // ---- + PD (bf16), mask, scale ----
#pragma unroll
        for (int nt = 0; nt < 8; nt++) {
            const int jc = j0 + nt * 8 + tig * 2;
            __nv_bfloat162 p0 = *(const __nv_bfloat162*)&PDb[(size_t)s_r0 * J_ + jc];
            __nv_bfloat162 p1 = *(const __nv_bfloat162*)&PDb[(size_t)s_r1 * J_ + jc];
            sc[nt][0] = (jc     <= s_r0 + P_)
                        ? (sc[nt][0] + __bfloat162float(p0.x)) * SCALE_ : -1.0e30f;
            sc[nt][1] = (jc + 1 <= s_r0 + P_)
                        ? (sc[nt][1] + __bfloat162float(p0.y)) * SCALE_ : -1.0e30f;
            sc[nt][2] = (jc     <= s_r1 + P_)
                        ? (sc[nt][2] + __bfloat162float(p1.x)) * SCALE_ : -1.0e30f;
            sc[nt][3] = (jc + 1 <= s_r1 + P_)
                        ? (sc[nt][3] + __bfloat162float(p1.y)) * SCALE_ : -1.0e30f;
        }

        // ---- online softmax ----
#pragma unroll
        for (int h = 0; h < 2; h++) {
            float mx = -3.0e38f;
#pragma unroll
            for (int nt = 0; nt < 8; nt++)
                mx = fmaxf(mx, fmaxf(sc[nt][2*h], sc[nt][2*h+1]));
            mx = fmaxf(mx, __shfl_xor_sync(0xffffffffu, mx, 1));
            mx = fmaxf(mx, __shfl_xor_sync(0xffffffffu, mx, 2));
            const float m_new = fmaxf(m_[h], mx);
            const float corr  = __expf(m_[h] - m_new);
            float sum = 0.f;
#pragma unroll
            for (int nt = 0; nt < 8; nt++) {
                float p0 = __expf(sc[nt][2*h]   - m_new);
                float p1 = __expf(sc[nt][2*h+1] - m_new);
                sc[nt][2*h] = p0; sc[nt][2*h+1] = p1;
                sum += p0 + p1;
            }
            sum += __shfl_xor_sync(0xffffffffu, sum, 1);
            sum += __shfl_xor_sync(0xffffffffu, sum, 2);
            l_[h] = l_[h] * corr + sum;
            m_[h] = m_new;
#pragma unroll
            for (int nt = 0; nt < 8; nt++) {
                o[nt][2*h]   *= corr;
                o[nt][2*h+1] *= corr;
            }
        }

        CP_WAIT1();
        __syncthreads();

        // ---- O += P @ V (3-term split) ----
        const uint32_t* vh32 = (const uint32_t*)sVh;
        const uint32_t* vl32 = (const uint32_t*)sVl;
#pragma unroll
        for (int ks = 0; ks < 4; ks++) {
            uint32_t ph[4], pl[4];
            split2(sc[2*ks][0],   sc[2*ks][1],   ph[0], pl[0]);
            split2(sc[2*ks][2],   sc[2*ks][3],   ph[1], pl[1]);
            split2(sc[2*ks+1][0], sc[2*ks+1][1], ph[2], pl[2]);
            split2(sc[2*ks+1][2], sc[2*ks+1][3], ph[3], pl[3]);
            const int w = ks * 8 + tig;
#pragma unroll
            for (int nt = 0; nt < 8; nt++) {
                const int nw = (nt * 8 + gid) * (FPAD/2);
                uint32_t bh2[2] = { vh32[nw + w], vh32[nw + w + 4] };
                uint32_t bl2[2] = { vl32[nw + w], vl32[nw + w + 4] };
                mma_bf16(o[nt], ph, bh2);
                mma_bf16(o[nt], ph, bl2);
                mma_bf16(o[nt], pl, bh2);
            }
        }

        __syncthreads();
        issueV(jn); CP_COMMIT();       // V_{t+1} loads during next scores
    }
    CP_WAIT0();

    // ---- epilogue: ctx[(s,b)][h*64+i] ----
    const float inv0 = 1.f / l_[0];
    const float inv1 = 1.f / l_[1];
    const int b = bh >> 4, hh = bh & 15;
#pragma unroll
    for (int nt = 0; nt < 8; nt++) {
        const int ic = hh * 64 + nt * 8 + tig * 2;
        *(float2*)&g_ctx[((size_t)(s_r0 * B_ + b)) * HI_ + ic] =
            make_float2(o[nt][0] * inv0, o[nt][1] * inv0);
        *(float2*)&g_ctx[((size_t)(s_r1 * B_ + b)) * HI_ + ic] =
            make_float2(o[nt][2] * inv1, o[nt][3] * inv1);
    }
}

// ------------------------------ layernorm ----------------------------------
__device__ __forceinline__ float warp_red_sum(float v) {
#pragma unroll
    for (int o = 16; o; o >>= 1) v += __shfl_xor_sync(0xffffffffu, v, o);
    return v;
}
__global__ void __launch_bounds__(256)
ln_kernel(const float* __restrict__ gamma, const float* __restrict__ beta,
          float* __restrict__ out) {
    const int row = blockIdx.x;
    const int tid = threadIdx.x;
    const float* p = g_proj + (size_t)row * E_;
    __shared__ float red[8];

    float v[4];
    float s = 0.f;
#pragma unroll
    for (int t = 0; t < 4; t++) { v[t] = p[tid + t*256]; s += v[t]; }
    s = warp_red_sum(s);
    if ((tid & 31) == 0) red[tid >> 5] = s;
    __syncthreads();
    float tot = 0.f;
#pragma unroll
    for (int w = 0; w < 8; w++) tot += red[w];
    const float mu = tot * (1.0f / E_);

    float vs = 0.f;
#pragma unroll
    for (int t = 0; t < 4; t++) { float d = v[t] - mu; vs += d * d; }
    vs = warp_red_sum(vs);
    __syncthreads();
    if ((tid & 31) == 0) red[tid >> 5] = vs;
    __syncthreads();
    float vtot = 0.f;
#pragma unroll
    for (int w = 0; w < 8; w++) vtot += red[w];
    const float inv = rsqrtf(vtot * (1.0f / E_) + EPS_);

#pragma unroll
    for (int t = 0; t < 4; t++) {
        int e = tid + t*256;
        out[(size_t)row * E_ + e] = (v[t] - mu) * inv * gamma[e] + beta[e];
    }
}

// ------------------------------- launch ------------------------------------
extern "C" void kernel_launch(void* const* d_in, const int* in_sizes, int n_in,
                              void* d_out, int out_size) {
    (void)in_sizes; (void)n_in; (void)out_size;
    const float* x     = (const float*)d_in[0];
    const float* rel   = (const float*)d_in[1];
    const float* mem   = (const float*)d_in[2];
    const float* u     = (const float*)d_in[3];
    const float* v     = (const float*)d_in[4];
    const float* Wkv   = (const float*)d_in[6];
    const float* Wq    = (const float*)d_in[7];
    const float* Wp    = (const float*)d_in[8];
    const float* Wo    = (const float*)d_in[9];
    const float* gamma = (const float*)d_in[10];
    const float* beta  = (const float*)d_in[11];
    float* out = (float*)d_out;

    // unconditional (no static guards); attribute calls are capture-safe
    cudaFuncSetAttribute(flash_mma,
                         cudaFuncAttributeMaxDynamicSharedMemorySize, FLASH_SMEM);
    cudaFuncSetAttribute(pd_kernel,
                         cudaFuncAttributeMaxDynamicSharedMemorySize, PD_SMEM);

    // 1. kv projection -> Khi (bf16), Vthi/Vtlo (split bf16, transposed)
    gemm_mma<<<dim3(2*HI_/128, J_*B_/128, 1), 256>>>(
        ALoadKV{mem, x}, BLoadW{Wkv, E_}, CStoreKV{}, E_);

    // 2. q projection -> quhi (+u), qvh (+v), both bf16
    gemm_mma<<<dim3(HI_/128, S_*B_/128, 1), 256>>>(
        ALoadPlain{x, E_}, BLoadW{Wq, E_}, CStoreQ{u, v}, E_);

    // 3. pos projection -> posh (bf16)
    gemm_mma<<<dim3(HI_/128, J_/128, 1), 256>>>(
        ALoadPlain{rel, E_}, BLoadW{Wp, E_}, CStorePos{}, E_);

    // 4. PD (dedicated bf16 kernel v2: 64-col subtiles, packed stores)
    pd_kernel<<<dim3(J_/256, S_/128, B_*H_), 256, PD_SMEM>>>();

    // 5. flash attention -> ctx
    flash_mma<<<dim3(S_/128, B_*H_), 256, FLASH_SMEM>>>();

    // 6. out projection + residual
    gemm_mma<<<dim3(E_/128, S_*B_/128, 1), 256>>>(
        ALoadCtx{}, BLoadW{Wo, HI_}, CStoreProj{x}, HI_);

    // 7. layernorm
    ln_kernel<<<S_*B_, 256>>>(gamma, beta, out);
}

// round 13
// speedup vs baseline: 1.4794x; 1.2098x over previous
#include <cuda_runtime.h>
#include <cuda_bf16.h>
#include <cstdint>

// ---------------------------------------------------------------------------
// Transformer-XL masked MHA. S=1024, P=1024, J=2048, B=2, E=1024, H=16, I=64.
// Softmax-side GEMMs (q, pos, K-proj, PD, scores): single-term bf16.
// Output-side GEMMs (V-proj, PV, out-proj): 3-term split-bf16 (fp32-grade).
// ---------------------------------------------------------------------------

constexpr int S_   = 1024;
constexpr int P_   = 1024;
constexpr int B_   = 2;
constexpr int E_   = 1024;
constexpr int H_   = 16;
constexpr int I_   = 64;
constexpr int J_   = 2048;
constexpr int HI_  = 1024;
constexpr float SCALE_ = 0.125f;
constexpr float EPS_   = 1e-5f;

// ------------------------- scratch (device globals) ------------------------
__device__ __nv_bfloat16 g_Khi [(size_t)B_*H_*J_*I_];  // [bh][j][i]
__device__ __nv_bfloat16 g_Vthi[(size_t)B_*H_*I_*J_];  // [bh][i][j] (transposed)
__device__ __nv_bfloat16 g_Vtlo[(size_t)B_*H_*I_*J_];
__device__ __nv_bfloat16 g_quhi[(size_t)B_*H_*S_*I_];  // [bh][s][i]
__device__ __nv_bfloat16 g_qvh [(size_t)B_*H_*S_*I_];  // [bh][s][i] bf16
__device__ __nv_bfloat16 g_posh[(size_t)H_*J_*I_];     // [h][r][i]  bf16
__device__ __nv_bfloat16 g_PD  [(size_t)B_*H_*S_*J_];  // pre-shifted [bh][s][j]
__device__ float g_ctx [(size_t)S_*B_*HI_];
__device__ float g_proj[(size_t)S_*B_*E_];

// ------------------------------ helpers ------------------------------------
__device__ __forceinline__ void split1(float x, __nv_bfloat16& h, __nv_bfloat16& l) {
    h = __float2bfloat16(x);
    l = __float2bfloat16(x - __bfloat162float(h));
}
__device__ __forceinline__ void split2(float x, float y,
                                       uint32_t& hi, uint32_t& lo) {
    __nv_bfloat162 h = __floats2bfloat162_rn(x, y);
    __nv_bfloat162 l = __floats2bfloat162_rn(x - __bfloat162float(h.x),
                                             y - __bfloat162float(h.y));
    hi = *(const uint32_t*)&h;
    lo = *(const uint32_t*)&l;
}
__device__ __forceinline__ uint32_t packbf2(float x, float y) {
    __nv_bfloat162 t = __floats2bfloat162_rn(x, y);
    return *(const uint32_t*)&t;
}
__device__ __forceinline__ void mma_bf16(float* d, const uint32_t* a,
                                         const uint32_t* b) {
    asm volatile(
        "mma.sync.aligned.m16n8k16.row.col.f32.bf16.bf16.f32 "
        "{%0,%1,%2,%3}, {%4,%5,%6,%7}, {%8,%9}, {%0,%1,%2,%3};"
        : "+f"(d[0]), "+f"(d[1]), "+f"(d[2]), "+f"(d[3])
        : "r"(a[0]), "r"(a[1]), "r"(a[2]), "r"(a[3]), "r"(b[0]), "r"(b[1]));
}

#define CP_ASYNC16(dst_u32, src_ptr) \
    asm volatile("cp.async.cg.shared.global [%0], [%1], 16;" \
                 :: "r"(dst_u32), "l"(src_ptr) : "memory")
#define CP_COMMIT() asm volatile("cp.async.commit_group;" ::: "memory")
#define CP_WAIT1()  asm volatile("cp.async.wait_group 1;" ::: "memory")
#define CP_WAIT0()  asm volatile("cp.async.wait_group 0;" ::: "memory")

// ------------------------------- functors ----------------------------------
struct ALoadKV {
    const float* mem; const float* x;
    __device__ __forceinline__ float4 operator()(int, int m, int k) const {
        const float* p = (m < P_*B_) ? (mem + (size_t)m*E_ + k)
                                     : (x + (size_t)(m - P_*B_)*E_ + k);
        return *(const float4*)p;
    }
};
struct ALoadPlain {
    const float* a; int K;
    __device__ __forceinline__ float4 operator()(int, int m, int k) const {
        return *(const float4*)(a + (size_t)m*K + k);
    }
};
struct ALoadCtx {
    __device__ __forceinline__ float4 operator()(int, int m, int k) const {
        return *(const float4*)&g_ctx[(size_t)m*HI_ + k];
    }
};
struct BLoadW {
    const float* w; int K;
    __device__ __forceinline__ float4 operator()(int, int n, int k) const {
        return *(const float4*)(w + (size_t)n*K + k);
    }
};

struct CStoreK {                    // K half of kv-proj (n in 0..HI-1)
    __device__ __forceinline__ void operator()(int, int m, int n, float c) const {
        int j = m / B_, b = m % B_;
        int hh = n >> 6, i = n & 63;
        g_Khi[(((size_t)(b*H_ + hh))*J_ + j)*I_ + i] = __float2bfloat16(c);
    }
};
struct CStoreV {                    // V half of kv-proj (n in 0..HI-1)
    __device__ __forceinline__ void operator()(int, int m, int n, float c) const {
        int j = m / B_, b = m % B_;
        int hh = n >> 6, i = n & 63;
        __nv_bfloat16 h, l;
        split1(c, h, l);
        size_t o = (((size_t)(b*H_ + hh))*I_ + i)*J_ + j;  // transposed
        g_Vthi[o] = h; g_Vtlo[o] = l;
    }
};
struct CStoreQ {
    const float* u; const float* v;
    __device__ __forceinline__ void operator()(int, int m, int n, float c) const {
        int s = m / B_, b = m % B_;
        int hh = n >> 6, i = n & 63;
        size_t o = (((size_t)(b*H_ + hh))*S_ + s)*I_ + i;
        g_quhi[o] = __float2bfloat16(c + u[n]);
        g_qvh[o]  = __float2bfloat16(c + v[n]);
    }
};
struct CStorePos {
    __device__ __forceinline__ void operator()(int, int m, int n, float c) const {
        int hh = n >> 6, i = n & 63;
        g_posh[((size_t)hh*J_ + m)*I_ + i] = __float2bfloat16(c);
    }
};
struct CStoreProj {
    const float* x;
    __device__ __forceinline__ void operator()(int, int m, int n, float c) const {
        g_proj[(size_t)m*E_ + n] = c + x[(size_t)m*E_ + n];
    }
};

// ------------------------- mma.sync GEMM (templated terms) -----------------
// SP=true: 3-term split-bf16 (fp32-grade). SP=false: single-term bf16.
// Round-6 schedule: store chunk -> sync -> prefetch next -> compute -> sync.
constexpr int SROW = 40;   // bf16 elements per smem row (32 data + 8 pad)

template<bool SP, class AL, class BL, class CS>
__global__ void __launch_bounds__(256)
gemm_mma(AL aload, BL bload, CS cstore, int K) {
    constexpr int NB = SP ? 2 : 1;
    __shared__ __nv_bfloat16 sA[NB][128 * SROW];
    __shared__ __nv_bfloat16 sB[NB][128 * SROW];

    const int tid  = threadIdx.x;
    const int wid  = tid >> 5;
    const int lane = tid & 31;
    const int gid  = lane >> 2;
    const int tig  = lane & 3;
    const int wm   = wid >> 2;
    const int wn   = wid & 3;
    const int m0   = blockIdx.y * 128;
    const int n0   = blockIdx.x * 128;
    const int bz   = blockIdx.z;

    float c[4][4][4];
#pragma unroll
    for (int mt = 0; mt < 4; mt++)
#pragma unroll
        for (int nt = 0; nt < 4; nt++)
#pragma unroll
            for (int r = 0; r < 4; r++) c[mt][nt][r] = 0.f;

    float4 av[4], bv[4];
#pragma unroll
    for (int q = 0; q < 4; q++) {
        const int f = tid + q * 256, row = f >> 3, kq = (f & 7) * 4;
        av[q] = aload(bz, m0 + row, kq);
        bv[q] = bload(bz, n0 + row, kq);
    }

    for (int k0 = 0; k0 < K; k0 += 32) {
        // ---- store current chunk ----
#pragma unroll
        for (int q = 0; q < 4; q++) {
            const int f = tid + q * 256, row = f >> 3, kq = (f & 7) * 4;
            const int so = row * SROW + kq;
            if constexpr (SP) {
                uint32_t h0, l0, h1, l1;
                split2(av[q].x, av[q].y, h0, l0);
                split2(av[q].z, av[q].w, h1, l1);
                *(uint2*)&sA[0][so] = make_uint2(h0, h1);
                *(uint2*)&sA[1][so] = make_uint2(l0, l1);
                split2(bv[q].x, bv[q].y, h0, l0);
                split2(bv[q].z, bv[q].w, h1, l1);
                *(uint2*)&sB[0][so] = make_uint2(h0, h1);
                *(uint2*)&sB[1][so] = make_uint2(l0, l1);
            } else {
                *(uint2*)&sA[0][so] = make_uint2(packbf2(av[q].x, av[q].y),
                                                 packbf2(av[q].z, av[q].w));
                *(uint2*)&sB[0][so] = make_uint2(packbf2(bv[q].x, bv[q].y),
                                                 packbf2(bv[q].z, bv[q].w));
            }
        }
        __syncthreads();

        // ---- prefetch next chunk ----
        if (k0 + 32 < K) {
#pragma unroll
            for (int q = 0; q < 4; q++) {
                const int f = tid + q * 256, row = f >> 3, kq = (f & 7) * 4;
                av[q] = aload(bz, m0 + row, k0 + 32 + kq);
                bv[q] = bload(bz, n0 + row, k0 + 32 + kq);
            }
        }

        // ---- compute ----
#pragma unroll
        for (int ks = 0; ks < 2; ks++) {
            const int kk = ks * 16 + tig * 2;
            uint32_t ah[4][4], al[4][4];
#pragma unroll
            for (int mt = 0; mt < 4; mt++) {
                const int m = wm * 64 + mt * 16 + gid;
                ah[mt][0] = *(const uint32_t*)&sA[0][m * SROW + kk];
                ah[mt][1] = *(const uint32_t*)&sA[0][(m + 8) * SROW + kk];
                ah[mt][2] = *(const uint32_t*)&sA[0][m * SROW + kk + 8];
                ah[mt][3] = *(const uint32_t*)&sA[0][(m + 8) * SROW + kk + 8];
                if constexpr (SP) {
                    al[mt][0] = *(const uint32_t*)&sA[1][m * SROW + kk];
                    al[mt][1] = *(const uint32_t*)&sA[1][(m + 8) * SROW + kk];
                    al[mt][2] = *(const uint32_t*)&sA[1][m * SROW + kk + 8];
                    al[mt][3] = *(const uint32_t*)&sA[1][(m + 8) * SROW + kk + 8];
                }
            }
#pragma unroll
            for (int nt = 0; nt < 4; nt++) {
                const int n = wn * 32 + nt * 8 + gid;
                uint32_t bh[2], bl[2];
                bh[0] = *(const uint32_t*)&sB[0][n * SROW + kk];
                bh[1] = *(const uint32_t*)&sB[0][n * SROW + kk + 8];
                if constexpr (SP) {
                    bl[0] = *(const uint32_t*)&sB[1][n * SROW + kk];
                    bl[1] = *(const uint32_t*)&sB[1][n * SROW + kk + 8];
                }
#pragma unroll
                for (int mt = 0; mt < 4; mt++) {
                    mma_bf16(c[mt][nt], ah[mt], bh);
                    if constexpr (SP) {
                        mma_bf16(c[mt][nt], ah[mt], bl);
                        mma_bf16(c[mt][nt], al[mt], bh);
                    }
                }
            }
        }
        __syncthreads();
    }

#pragma unroll
    for (int mt = 0; mt < 4; mt++) {
        const int gm = m0 + wm * 64 + mt * 16 + gid;
#pragma unroll
        for (int nt = 0; nt < 4; nt++) {
            const int gn = n0 + wn * 32 + nt * 8 + tig * 2;
            cstore(bz, gm,     gn,     c[mt][nt][0]);
            cstore(bz, gm,     gn + 1, c[mt][nt][1]);
            cstore(bz, gm + 8, gn,     c[mt][nt][2]);
            cstore(bz, gm + 8, gn + 1, c[mt][nt][3]);
        }
    }
}

// ----------------------- PD kernel v3 (pure bf16, K=64) --------------------
// PD[bh][s][j] = qv_s . pos_{j+1023-s}  stored pre-shifted in bf16.
// Block: 128 rows x 256 cols (4 n-subtiles of 64 sharing the smem A tile).
// grid (J/256, S/128, B*H). Epilogue: warp-local smem staging -> full-row
// coalesced 128B stores (funnel-shift for odd-j0 rows).
constexpr int PDW = 36;                       // words per smem row (72 bf16)
constexpr int PD_SMEM = (128 + 64 + 64 + 128) * 72 * 2;   // +sOut = 55296 B

__global__ void __launch_bounds__(256) pd_kernel() {
    extern __shared__ __nv_bfloat16 psm[];
    __nv_bfloat16* sA   = psm;                // [128][72]
    __nv_bfloat16* sB0  = sA  + 128 * 72;     // [64][72]
    __nv_bfloat16* sB1  = sB0 + 64 * 72;
    __nv_bfloat16* sOut = sB1 + 64 * 72;      // [128][72] staging

    const int tid  = threadIdx.x;
    const int wq   = tid >> 5;
    const int lane = tid & 31;
    const int gid  = lane >> 2;
    const int tig  = lane & 3;
    const int m0   = blockIdx.y * 128;
    const int ng   = blockIdx.x * 256;
    const int bh   = blockIdx.z;

    // subtile ns has a valid element iff m0+127 + (ng+ns*64)+63 >= 1023
    int need = 833 - m0 - ng;
    int ns_min = (need <= 0) ? 0 : ((need + 63) >> 6);
    if (ns_min > 3) return;

    const int arow = tid >> 1;
    const int aw   = (tid & 1) * 16;
    const int brow = tid >> 2;
    const int bw   = (tid & 3) * 8;

    auto issueA = [&]() {
        const char* src = (const char*)((const uint32_t*)
            (g_qvh + ((size_t)bh * S_ + m0 + arow) * I_) + aw);
        uint32_t dst = (uint32_t)__cvta_generic_to_shared(
            (uint32_t*)&sA[arow * 72] + aw);
        CP_ASYNC16(dst,      src);
        CP_ASYNC16(dst + 16, src + 16);
        CP_ASYNC16(dst + 32, src + 32);
        CP_ASYNC16(dst + 48, src + 48);
    };
    auto issueB = [&](int ns, __nv_bfloat16* buf) {
        const int n0 = ng + ns * 64;
        const char* src = (const char*)((const uint32_t*)
            (g_posh + ((size_t)(bh & 15) * J_ + n0 + brow) * I_) + bw);
        uint32_t dst = (uint32_t)__cvta_generic_to_shared(
            (uint32_t*)&buf[brow * 72] + bw);
        CP_ASYNC16(dst,      src);
        CP_ASYNC16(dst + 16, src + 16);
    };

    issueA();
    issueB(ns_min, sB0);
    CP_COMMIT();
    if (ns_min + 1 <= 3) { issueB(ns_min + 1, sB1); CP_COMMIT(); }

    const int r0w = (wq * 16 + gid) * PDW;

    for (int ns = ns_min; ns <= 3; ns++) {
        const int idx = ns - ns_min;
        if (ns + 1 <= 3) CP_WAIT1(); else CP_WAIT0();
        __syncthreads();

        const uint32_t* qa = (const uint32_t*)sA;
        const uint32_t* qb = (const uint32_t*)((idx & 1) ? sB1 : sB0);

        float c[8][4];
#pragma unroll
        for (int nt = 0; nt < 8; nt++)
#pragma unroll
            for (int r = 0; r < 4; r++) c[nt][r] = 0.f;

#pragma unroll
        for (int ks = 0; ks < 4; ks++) {
            const int w = ks * 8 + tig;
            uint32_t a[4];
            a[0] = qa[r0w + w];
            a[1] = qa[r0w + 8 * PDW + w];
            a[2] = qa[r0w + w + 4];
            a[3] = qa[r0w + 8 * PDW + w + 4];
#pragma unroll
            for (int nt = 0; nt < 8; nt++) {
                const int nw = (nt * 8 + gid) * PDW;
                uint32_t b2[2] = { qb[nw + w], qb[nw + w + 4] };
                mma_bf16(c[nt], a, b2);
            }
        }
        __syncthreads();
        if (ns + 2 <= 3) { issueB(ns + 2, (idx & 1) ? sB1 : sB0); CP_COMMIT(); }

        // ---- stage fragments into sOut (warp-local rows wq*16..+15) ----
        {
            const int r0s = (wq * 16 + gid) * 72;
#pragma unroll
            for (int nt = 0; nt < 8; nt++) {
                *(uint32_t*)&sOut[r0s + nt * 8 + tig * 2] =
                    packbf2(c[nt][0], c[nt][1]);
                *(uint32_t*)&sOut[r0s + 8 * 72 + nt * 8 + tig * 2] =
                    packbf2(c[nt][2], c[nt][3]);
            }
        }
        __syncwarp();

        // ---- coalesced row stores: warp streams its own 16 rows ----
        const int n0s = ng + ns * 64;
#pragma unroll
        for (int it = 0; it < 16; it++) {
            const int r  = wq * 16 + it;
            const int gm = m0 + r;
            const int jr = n0s + gm - 1023;
            if (jr + 63 < 0) continue;
            const uint32_t* srow = (const uint32_t*)&sOut[r * 72];
            __nv_bfloat16* drow = g_PD + ((size_t)bh * S_ + gm) * J_;
            if ((jr & 1) == 0) {
                const int j = jr + lane * 2;
                if (j >= 0) *(uint32_t*)&drow[j] = srow[lane];
            } else {
                if (lane < 31) {
                    const int j = jr + 1 + lane * 2;
                    if (j >= 0) {
                        uint32_t w0 = srow[lane], w1 = srow[lane + 1];
                        *(uint32_t*)&drow[j] = (w0 >> 16) | (w1 << 16);
                    }
                } else {
                    if (jr >= 0)      drow[jr]      = sOut[r * 72];
                    if (jr + 63 >= 0) drow[jr + 63] = sOut[r * 72 + 63];
                }
            }
        }
    }
}

// ---------------------------- flash attention (MMA) ------------------------
// grid (S/128, B*H), 256 threads = 8 warps; warp wq owns rows wq*16..+15.
// j-tiles of 64, cp.async pipelined K/V. Scores: single-term bf16.
// PV: 3-term split (Ph*Vh + Ph*Vl + Pl*Vh).
constexpr int FPAD = 72;
constexpr int FLASH_SMEM = (128 + 64 + 128) * FPAD * 2;  // 46080 B

__global__ void __launch_bounds__(256) flash_mma() {
    extern __shared__ __nv_bfloat16 fsm[];
    __nv_bfloat16* sQh = fsm;                    // [s][i] 128x72
    __nv_bfloat16* sKh = sQh + 128 * FPAD;       // [j][i] 64x72
    __nv_bfloat16* sVh = sKh + 64 * FPAD;        // [i][j] 64x72
    __nv_bfloat16* sVl = sVh + 64 * FPAD;

    const int tid  = threadIdx.x;
    const int wq   = tid >> 5;
    const int lane = tid & 31;
    const int gid  = lane >> 2;
    const int tig  = lane & 3;
    // heavy s-blocks launch first
    const int s0   = (gridDim.x - 1 - blockIdx.x) * 128;
    const int bh   = blockIdx.y;

    const int s_r0 = s0 + wq * 16 + gid;
    const int s_r1 = s_r0 + 8;

    const int row4 = tid >> 2;            // 0..63
    const int qw   = (tid & 3) * 8;       // word offset

    auto issueK = [&](int j0) {
        const char* srch = (const char*)((const uint32_t*)
            (g_Khi + (((size_t)bh * J_) + j0 + row4) * I_) + qw);
        uint32_t dh = (uint32_t)__cvta_generic_to_shared(
            (uint32_t*)&sKh[row4 * FPAD] + qw);
        CP_ASYNC16(dh,      srch);
        CP_ASYNC16(dh + 16, srch + 16);
    };
    auto issueV = [&](int j0) {
        const char* srch = (const char*)((const uint32_t*)
            (g_Vthi + ((size_t)bh * I_ + row4) * J_ + j0) + qw);
        const char* srcl = (const char*)((const uint32_t*)
            (g_Vtlo + ((size_t)bh * I_ + row4) * J_ + j0) + qw);
        uint32_t dh = (uint32_t)__cvta_generic_to_shared(
            (uint32_t*)&sVh[row4 * FPAD] + qw);
        uint32_t dl = (uint32_t)__cvta_generic_to_shared(
            (uint32_t*)&sVl[row4 * FPAD] + qw);
        CP_ASYNC16(dh,      srch);
        CP_ASYNC16(dh + 16, srch + 16);
        CP_ASYNC16(dl,      srcl);
        CP_ASYNC16(dl + 16, srcl + 16);
    };

    issueK(0); CP_COMMIT();
    issueV(0); CP_COMMIT();

    // ---- load Q tile (hi only) ----
    {
        const int row  = tid >> 1;
        const int half = (tid & 1) * 16;
        const uint4* srch = (const uint4*)((const uint32_t*)
            (g_quhi + ((size_t)bh * S_ + s0 + row) * I_) + half);
        uint4* dsth = (uint4*)((uint32_t*)&sQh[row * FPAD] + half);
#pragma unroll
        for (int q = 0; q < 4; q++) dsth[q] = srch[q];
    }

    const __nv_bfloat16* PDb = g_PD + (size_t)bh * S_ * J_;

    float m_[2] = {-3.0e38f, -3.0e38f};
    float l_[2] = {0.f, 0.f};
    float o[8][4];
#pragma unroll
    for (int nt = 0; nt < 8; nt++)
#pragma unroll
        for (int r = 0; r < 4; r++) o[nt][r] = 0.f;

    const int ntiles = min(32, s0 / 64 + 18);
    for (int jt = 0; jt < ntiles; jt++) {
        const int j0 = jt * 64;
        const int jn = min(jt + 1, ntiles - 1) * 64;   // clamped prefetch

        CP_WAIT1();
        __syncthreads();

        // ---- scores S = Q @ K^T (single-term bf16) ----
        float sc[8][4];
#pragma unroll
        for (int nt = 0; nt < 8; nt++)
#pragma unroll
            for (int r = 0; r < 4; r++) sc[nt][r] = 0.f;

        const uint32_t* qh32 = (const uint32_t*)sQh;
        const uint32_t* kh32 = (const uint32_t*)sKh;
        const int r0w = (wq * 16 + gid) * (FPAD/2);
        const int r1w = r0w + 8 * (FPAD/2);
#pragma unroll
        for (int ks = 0; ks < 4; ks++) {
            const int w = ks * 8 + tig;
            uint32_t ah[4];
            ah[0] = qh32[r0w + w];     ah[1] = qh32[r1w + w];
            ah[2] = qh32[r0w + w + 4]; ah[3] = qh32[r1w + w + 4];
#pragma unroll
            for (int nt = 0; nt < 8; nt++) {
                const int nw = (nt * 8 + gid) * (FPAD/2);
                uint32_t bh2[2] = { kh32[nw + w], kh32[nw + w + 4] };
                mma_bf16(sc[nt], ah, bh2);
            }
        }

        __syncthreads();               // all warps done reading K_t
        issueK(jn); CP_COMMIT();       // K_{t+1} loads during softmax + PV

        // ---- + PD (bf16), mask, scale ----
#pragma unroll
        for (int nt = 0; nt < 8; nt++) {
            const int jc = j0 + nt * 8 + tig * 2;
            __nv_bfloat162 p0 = *(const __nv_bfloat162*)&PDb[(size_t)s_r0 * J_ + jc];
            __nv_bfloat162 p1 = *(const __nv_bfloat162*)&PDb[(size_t)s_r1 * J_ + jc];
            sc[nt][0] = (jc     <= s_r0 + P_)
                        ? (sc[nt][0] + __bfloat162float(p0.x)) * SCALE_ : -1.0e30f;
            sc[nt][1] = (jc + 1 <= s_r0 + P_)
                        ? (sc[nt][1] + __bfloat162float(p0.y)) * SCALE_ : -1.0e30f;
            sc[nt][2] = (jc     <= s_r1 + P_)
                        ? (sc[nt][2] + __bfloat162float(p1.x)) * SCALE_ : -1.0e30f;
            sc[nt][3] = (jc + 1 <= s_r1 + P_)
                        ? (sc[nt][3] + __bfloat162float(p1.y)) * SCALE_ : -1.0e30f;
        }

        // ---- online softmax ----
#pragma unroll
        for (int h = 0; h < 2; h++) {
            float mx = -3.0e38f;
#pragma unroll
            for (int nt = 0; nt < 8; nt++)
                mx = fmaxf(mx, fmaxf(sc[nt][2*h], sc[nt][2*h+1]));
            mx = fmaxf(mx, __shfl_xor_sync(0xffffffffu, mx, 1));
            mx = fmaxf(mx, __shfl_xor_sync(0xffffffffu, mx, 2));
            const float m_new = fmaxf(m_[h], mx);
            const float corr  = __expf(m_[h] - m_new);
            float sum = 0.f;
#pragma unroll
            for (int nt = 0; nt < 8; nt++) {
                float p0 = __expf(sc[nt][2*h]   - m_new);
                float p1 = __expf(sc[nt][2*h+1] - m_new);
                sc[nt][2*h] = p0; sc[nt][2*h+1] = p1;
                sum += p0 + p1;
            }
            sum += __shfl_xor_sync(0xffffffffu, sum, 1);
            sum += __shfl_xor_sync(0xffffffffu, sum, 2);
            l_[h] = l_[h] * corr + sum;
            m_[h] = m_new;
#pragma unroll
            for (int nt = 0; nt < 8; nt++) {
                o[nt][2*h]   *= corr;
                o[nt][2*h+1] *= corr;
            }
        }

        CP_WAIT1();
        __syncthreads();

        // ---- O += P @ V (3-term split) ----
        const uint32_t* vh32 = (const uint32_t*)sVh;
        const uint32_t* vl32 = (const uint32_t*)sVl;
#pragma unroll
        for (int ks = 0; ks < 4; ks++) {
            uint32_t ph[4], pl[4];
            split2(sc[2*ks][0],   sc[2*ks][1],   ph[0], pl[0]);
            split2(sc[2*ks][2],   sc[2*ks][3],   ph[1], pl[1]);
            split2(sc[2*ks+1][0], sc[2*ks+1][1], ph[2], pl[2]);
            split2(sc[2*ks+1][2], sc[2*ks+1][3], ph[3], pl[3]);
            const int w = ks * 8 + tig;
#pragma unroll
            for (int nt = 0; nt < 8; nt++) {
                const int nw = (nt * 8 + gid) * (FPAD/2);
                uint32_t bh2[2] = { vh32[nw + w], vh32[nw + w + 4] };
                uint32_t bl2[2] = { vl32[nw + w], vl32[nw + w + 4] };
                mma_bf16(o[nt], ph, bh2);
                mma_bf16(o[nt], ph, bl2);
                mma_bf16(o[nt], pl, bh2);
            }
        }

        __syncthreads();
        issueV(jn); CP_COMMIT();       // V_{t+1} loads during next scores
    }
    CP_WAIT0();

    // ---- epilogue: ctx[(s,b)][h*64+i] ----
    const float inv0 = 1.f / l_[0];
    const float inv1 = 1.f / l_[1];
    const int b = bh >> 4, hh = bh & 15;
#pragma unroll
    for (int nt = 0; nt < 8; nt++) {
        const int ic = hh * 64 + nt * 8 + tig * 2;
        *(float2*)&g_ctx[((size_t)(s_r0 * B_ + b)) * HI_ + ic] =
            make_float2(o[nt][0] * inv0, o[nt][1] * inv0);
        *(float2*)&g_ctx[((size_t)(s_r1 * B_ + b)) * HI_ + ic] =
            make_float2(o[nt][2] * inv1, o[nt][3] * inv1);
    }
}

// ------------------------------ layernorm ----------------------------------
__device__ __forceinline__ float warp_red_sum(float v) {
#pragma unroll
    for (int o = 16; o; o >>= 1) v += __shfl_xor_sync(0xffffffffu, v, o);
    return v;
}
__global__ void __launch_bounds__(256)
ln_kernel(const float* __restrict__ gamma, const float* __restrict__ beta,
          float* __restrict__ out) {
    const int row = blockIdx.x;
    const int tid = threadIdx.x;
    const float* p = g_proj + (size_t)row * E_;
    __shared__ float red[8];

    float v[4];
    float s = 0.f;
#pragma unroll
    for (int t = 0; t < 4; t++) { v[t] = p[tid + t*256]; s += v[t]; }
    s = warp_red_sum(s);
    if ((tid & 31) == 0) red[tid >> 5] = s;
    __syncthreads();
    float tot = 0.f;
#pragma unroll
    for (int w = 0; w < 8; w++) tot += red[w];
    const float mu = tot * (1.0f / E_);

    float vs = 0.f;
#pragma unroll
    for (int t = 0; t < 4; t++) { float d = v[t] - mu; vs += d * d; }
    vs = warp_red_sum(vs);
    __syncthreads();
    if ((tid & 31) == 0) red[tid >> 5] = vs;
    __syncthreads();
    float vtot = 0.f;
#pragma unroll
    for (int w = 0; w < 8; w++) vtot += red[w];
    const float inv = rsqrtf(vtot * (1.0f / E_) + EPS_);

#pragma unroll
    for (int t = 0; t < 4; t++) {
        int e = tid + t*256;
        out[(size_t)row * E_ + e] = (v[t] - mu) * inv * gamma[e] + beta[e];
    }
}

// ------------------------------- launch ------------------------------------
extern "C" void kernel_launch(void* const* d_in, const int* in_sizes, int n_in,
                              void* d_out, int out_size) {
    (void)in_sizes; (void)n_in; (void)out_size;
    const float* x     = (const float*)d_in[0];
    const float* rel   = (const float*)d_in[1];
    const float* mem   = (const float*)d_in[2];
    const float* u     = (const float*)d_in[3];
    const float* v     = (const float*)d_in[4];
    const float* Wkv   = (const float*)d_in[6];
    const float* Wq    = (const float*)d_in[7];
    const float* Wp    = (const float*)d_in[8];
    const float* Wo    = (const float*)d_in[9];
    const float* gamma = (const float*)d_in[10];
    const float* beta  = (const float*)d_in[11];
    float* out = (float*)d_out;

    // unconditional (no static guards); attribute calls are capture-safe
    cudaFuncSetAttribute(flash_mma,
                         cudaFuncAttributeMaxDynamicSharedMemorySize, FLASH_SMEM);
    cudaFuncSetAttribute(pd_kernel,
                         cudaFuncAttributeMaxDynamicSharedMemorySize, PD_SMEM);

    // 1a. K projection (single-term) -> Khi
    gemm_mma<false><<<dim3(HI_/128, J_*B_/128, 1), 256>>>(
        ALoadKV{mem, x}, BLoadW{Wkv, E_}, CStoreK{}, E_);

    // 1b. V projection (3-term) -> Vthi/Vtlo (transposed)
    gemm_mma<true><<<dim3(HI_/128, J_*B_/128, 1), 256>>>(
        ALoadKV{mem, x}, BLoadW{Wkv + (size_t)HI_ * E_, E_}, CStoreV{}, E_);

    // 2. q projection (single-term) -> quhi (+u), qvh (+v)
    gemm_mma<false><<<dim3(HI_/128, S_*B_/128, 1), 256>>>(
        ALoadPlain{x, E_}, BLoadW{Wq, E_}, CStoreQ{u, v}, E_);

    // 3. pos projection (single-term) -> posh
    gemm_mma<false><<<dim3(HI_/128, J_/128, 1), 256>>>(
        ALoadPlain{rel, E_}, BLoadW{Wp, E_}, CStorePos{}, E_);

    // 4. PD (bf16 kernel v3: coalesced staged stores)
    pd_kernel<<<dim3(J_/256, S_/128, B_*H_), 256, PD_SMEM>>>();

    // 5. flash attention -> ctx
    flash_mma<<<dim3(S_/128, B_*H_), 256, FLASH_SMEM>>>();

    // 6. out projection + residual (3-term)
    gemm_mma<true><<<dim3(E_/128, S_*B_/128, 1), 256>>>(
        ALoadCtx{}, BLoadW{Wo, HI_}, CStoreProj{x}, HI_);

    // 7. layernorm
    ln_kernel<<<S_*B_, 256>>>(gamma, beta, out);
}